// round 3
// baseline (speedup 1.0000x reference)
#include <cuda_runtime.h>
#include <math.h>

// ---------------- problem constants ----------------
#define BATCH     16
#define SEQLEN    512
#define DMODEL    1024
#define DSTATE    128
#define DCONV     4
#define HEADDIM   64
#define DSSM      2048
#define NHEADS    32
#define CONVDIM   2304            // DSSM + 2*DSTATE
#define DINPROJ   4384            // 2*DSSM + 2*DSTATE + NHEADS
#define ACTDIM    2336            // CONVDIM + NHEADS
#define NCTA      128
#define NTHR      512
#define EPSV      1e-5f

// ---------------- device scratch (no allocations allowed) ----------------
__device__ float g_zxbcdt[BATCH * SEQLEN * DINPROJ];    // in_proj output
__device__ float g_xbcconv[BATCH * SEQLEN * CONVDIM];   // conv output
__device__ float g_act[BATCH * ACTDIM];                 // per-step silu(xBC) | silu(dtr)
__device__ float g_yn[BATCH * DSSM];                    // per-step normalized y (carry)
__device__ float g_mspart[SEQLEN * BATCH * 32];         // RMS partials (fixed slots)
__device__ int   g_mscnt[SEQLEN * BATCH];               // RMS arrival counters
__device__ unsigned g_bar_cnt;
__device__ unsigned g_bar_gen;

// ---------------- helpers ----------------
__device__ __forceinline__ float silu_f(float v) {
    return v / (1.0f + expf(-v));
}
__device__ __forceinline__ float softplus_f(float v) {
    return (v > 20.0f) ? v : log1pf(expf(v));
}

// sense-reversing grid barrier; all NCTA CTAs co-resident (1 CTA/SM, single wave)
__device__ __forceinline__ void grid_barrier() {
    __threadfence();
    __syncthreads();
    if (threadIdx.x == 0) {
        unsigned old = *((volatile unsigned*)&g_bar_gen);
        unsigned a = atomicAdd(&g_bar_cnt, 1u);
        if (a == (unsigned)(NCTA - 1)) {
            atomicExch(&g_bar_cnt, 0u);
            __threadfence();
            atomicAdd(&g_bar_gen, 1u);
        } else {
            while (*((volatile unsigned*)&g_bar_gen) == old) { __nanosleep(64); }
        }
        __threadfence();
    }
    __syncthreads();
}

// ---------------- kernel 1: in_proj GEMM  C[8192,4384] = U[8192,1024] @ Win[4384,1024]^T ----
__global__ __launch_bounds__(256) void inproj_kernel(const float* __restrict__ U,
                                                     const float* __restrict__ Win) {
    const int M = BATCH * SEQLEN;   // 8192
    const int N = DINPROJ;          // 4384
    const int K = DMODEL;           // 1024

    __shared__ float As[32][68];    // [k][m]
    __shared__ float Bs[32][68];    // [k][n]

    const int tid   = threadIdx.x;
    const int mbase = blockIdx.y * 64;
    const int nbase = blockIdx.x * 64;
    const int lr = tid >> 3;          // 0..31
    const int lc = (tid & 7) << 2;    // 0,4,...,28
    const int ty = tid >> 4;          // 0..15
    const int tx = tid & 15;          // 0..15

    float acc[4][4];
#pragma unroll
    for (int i = 0; i < 4; i++)
#pragma unroll
        for (int j = 0; j < 4; j++) acc[i][j] = 0.0f;

    for (int k0 = 0; k0 < K; k0 += 32) {
        float4 a0 = *(const float4*)(U + (mbase + lr) * K + k0 + lc);
        float4 a1 = *(const float4*)(U + (mbase + lr + 32) * K + k0 + lc);
        float4 b0 = make_float4(0.f, 0.f, 0.f, 0.f);
        float4 b1 = make_float4(0.f, 0.f, 0.f, 0.f);
        if (nbase + lr < N)      b0 = *(const float4*)(Win + (nbase + lr) * K + k0 + lc);
        if (nbase + lr + 32 < N) b1 = *(const float4*)(Win + (nbase + lr + 32) * K + k0 + lc);

        __syncthreads();
        As[lc + 0][lr] = a0.x; As[lc + 1][lr] = a0.y; As[lc + 2][lr] = a0.z; As[lc + 3][lr] = a0.w;
        As[lc + 0][lr + 32] = a1.x; As[lc + 1][lr + 32] = a1.y; As[lc + 2][lr + 32] = a1.z; As[lc + 3][lr + 32] = a1.w;
        Bs[lc + 0][lr] = b0.x; Bs[lc + 1][lr] = b0.y; Bs[lc + 2][lr] = b0.z; Bs[lc + 3][lr] = b0.w;
        Bs[lc + 0][lr + 32] = b1.x; Bs[lc + 1][lr + 32] = b1.y; Bs[lc + 2][lr + 32] = b1.z; Bs[lc + 3][lr + 32] = b1.w;
        __syncthreads();

#pragma unroll
        for (int kk = 0; kk < 32; kk++) {
            float4 av = *(const float4*)&As[kk][ty * 4];
            float4 bv = *(const float4*)&Bs[kk][tx * 4];
            float a[4] = {av.x, av.y, av.z, av.w};
            float b[4] = {bv.x, bv.y, bv.z, bv.w};
#pragma unroll
            for (int i = 0; i < 4; i++)
#pragma unroll
                for (int j = 0; j < 4; j++) acc[i][j] = fmaf(a[i], b[j], acc[i][j]);
        }
    }

#pragma unroll
    for (int i = 0; i < 4; i++) {
        int row = mbase + ty * 4 + i;
#pragma unroll
        for (int j = 0; j < 4; j++) {
            int col = nbase + tx * 4 + j;
            if (col < N) g_zxbcdt[row * N + col] = acc[i][j];
        }
    }
}

// ---------------- kernel 2: causal depthwise conv over L ----------------
__global__ __launch_bounds__(256) void conv_kernel(const float* __restrict__ conv_w,
                                                   const float* __restrict__ conv_b) {
    int idx = blockIdx.x * blockDim.x + threadIdx.x;
    if (idx >= BATCH * SEQLEN * CONVDIM) return;
    int c  = idx % CONVDIM;
    int bt = idx / CONVDIM;
    int t  = bt % SEQLEN;
    int b  = bt / SEQLEN;
    float accv = conv_b[c];
#pragma unroll
    for (int k = 0; k < DCONV; k++) {
        int tt = t + k - (DCONV - 1);
        if (tt >= 0)
            accv = fmaf(g_zxbcdt[(b * SEQLEN + tt) * DINPROJ + DSSM + c],
                        conv_w[c * DCONV + k], accv);
    }
    g_xbcconv[idx] = accv;
}

// ---------------- kernel 3: persistent sequential scan ----------------
// CTA c: head h = c & 31, batch-group bg = c >> 5 (batches 4bg..4bg+3).
// Phase A tasks (matvecs vs yn(t-1)): 18 W_rxbc rows, 1 W_rdt row (cta<32), 8 W_out rows.
// Phase B: SMEM-resident state update + cross-CTA RMS norm + yn write.
__global__ __launch_bounds__(NTHR, 1) void scan_kernel(
    const float* __restrict__ W_rxbc, const float* __restrict__ W_rdt,
    const float* __restrict__ dt_bias, const float* __restrict__ A_log,
    const float* __restrict__ D_param, const float* __restrict__ norm_w,
    const float* __restrict__ W_out, float* __restrict__ out) {

    extern __shared__ float sm[];
    float* s_state = sm;                 // 32768 floats: state[n][pair], pair = b_loc*64+d
    float* s_bc    = sm + 32768;         // 1024 floats: [b_loc][0..127]=Bv, [128..255]=Cv
    float* s_red   = sm + 32768 + 1024;  // 16 floats

    const int tid  = threadIdx.x;
    const int cta  = blockIdx.x;
    const int lane = tid & 31;
    const int warp = tid >> 5;

    // ---- per-launch init ----
    for (int i = cta * NTHR + tid; i < BATCH * DSSM; i += NCTA * NTHR) g_yn[i] = 0.0f;
    for (int i = cta * NTHR + tid; i < SEQLEN * BATCH; i += NCTA * NTHR) g_mscnt[i] = 0;
    for (int i = tid; i < 4 * DSTATE * HEADDIM; i += NTHR) s_state[i] = 0.0f;

    // ---- phase A task setup (t-invariant) ----
    const int hasdt = (cta < NHEADS) ? 1 : 0;
    const int ntask = 18 + hasdt + 8;     // 26 or 27
    const int r0i = warp * 2, r1i = warp * 2 + 1;
    const bool v0 = (r0i < ntask);
    const bool v1 = (r1i < ntask);

    int type0 = 0, idx0 = 0, type1 = 0, idx1 = 0;
    const float* w0 = W_rxbc;
    const float* w1 = W_rxbc;
    if (v0) {
        int r = r0i;
        if (r < 18) { type0 = 0; idx0 = cta * 18 + r; w0 = W_rxbc + idx0 * DSSM; }
        else {
            r -= 18;
            if (hasdt && r == 0) { type0 = 1; idx0 = cta; w0 = W_rdt + cta * DSSM; }
            else { r -= hasdt; type0 = 2; idx0 = cta * 8 + r; w0 = W_out + idx0 * DSSM; }
        }
    }
    if (v1) {
        int r = r1i;
        if (r < 18) { type1 = 0; idx1 = cta * 18 + r; w1 = W_rxbc + idx1 * DSSM; }
        else {
            r -= 18;
            if (hasdt && r == 0) { type1 = 1; idx1 = cta; w1 = W_rdt + cta * DSSM; }
            else { r -= hasdt; type1 = 2; idx1 = cta * 8 + r; w1 = W_out + idx1 * DSSM; }
        }
    } else {
        w1 = w0; type1 = type0; idx1 = idx0;
    }

    // ---- phase B constants ----
    const int h  = cta & 31;
    const int bg = cta >> 5;
    const int b_loc = (tid < 256) ? (tid >> 6) : 0;
    const int dd    = (tid < 256) ? (tid & 63) : 0;
    const int bglb  = bg * 4 + b_loc;          // global batch
    const float Ah  = -expf(A_log[h]);
    const float dtb = dt_bias[h];
    const float Dh  = D_param[h];
    const float nw  = norm_w[h * HEADDIM + dd];

    grid_barrier();   // init done everywhere

    for (int t = 0; t <= SEQLEN; t++) {
        // =================== phase A: matvecs vs yn(t-1) ===================
        bool compute = v0 && (t < SEQLEN || type0 == 2 || (v1 && type1 == 2));
        if (compute) {
            float acc0[16], acc1[16];
#pragma unroll
            for (int b = 0; b < 16; b++) { acc0[b] = 0.0f; acc1[b] = 0.0f; }

#pragma unroll 2
            for (int blk = 0; blk < 16; blk++) {
                int col = blk * 128 + lane * 4;
                float4 a = *(const float4*)(w0 + col);
                float4 c = *(const float4*)(w1 + col);
#pragma unroll
                for (int b = 0; b < 16; b++) {
                    float4 y = *(const float4*)(g_yn + b * DSSM + col);
                    acc0[b] = fmaf(a.x, y.x, fmaf(a.y, y.y, fmaf(a.z, y.z, fmaf(a.w, y.w, acc0[b]))));
                    acc1[b] = fmaf(c.x, y.x, fmaf(c.y, y.y, fmaf(c.z, y.z, fmaf(c.w, y.w, acc1[b]))));
                }
            }

            float out0 = 0.0f, out1 = 0.0f;
#pragma unroll
            for (int b = 0; b < 16; b++) {
                float s0 = acc0[b], s1 = acc1[b];
#pragma unroll
                for (int off = 16; off > 0; off >>= 1) {
                    s0 += __shfl_xor_sync(0xffffffffu, s0, off);
                    s1 += __shfl_xor_sync(0xffffffffu, s1, off);
                }
                if (lane == b) { out0 = s0; out1 = s1; }
            }

            if (lane < 16) {
                int b = lane;
                // row 0
                if (type0 == 0) {
                    if (t < SEQLEN) {
                        float base = g_xbcconv[(b * SEQLEN + t) * CONVDIM + idx0];
                        g_act[b * ACTDIM + idx0] = silu_f(base + out0);
                    }
                } else if (type0 == 1) {
                    if (t < SEQLEN) {
                        float base = g_zxbcdt[(b * SEQLEN + t) * DINPROJ + (DSSM + CONVDIM) + idx0];
                        g_act[b * ACTDIM + CONVDIM + idx0] = silu_f(base + out0);
                    }
                } else {
                    if (t >= 1) out[(b * SEQLEN + (t - 1)) * DMODEL + idx0] = out0;
                }
                // row 1
                if (v1) {
                    if (type1 == 0) {
                        if (t < SEQLEN) {
                            float base = g_xbcconv[(b * SEQLEN + t) * CONVDIM + idx1];
                            g_act[b * ACTDIM + idx1] = silu_f(base + out1);
                        }
                    } else if (type1 == 1) {
                        if (t < SEQLEN) {
                            float base = g_zxbcdt[(b * SEQLEN + t) * DINPROJ + (DSSM + CONVDIM) + idx1];
                            g_act[b * ACTDIM + CONVDIM + idx1] = silu_f(base + out1);
                        }
                    } else {
                        if (t >= 1) out[(b * SEQLEN + (t - 1)) * DMODEL + idx1] = out1;
                    }
                }
            }
        }

        if (t == SEQLEN) break;   // final pass only emitted out(L-1)

        grid_barrier();           // act(t) visible everywhere

        // =================== phase B: state update + norm ===================
        // load Bv|Cv for this CTA's 4 batches into SMEM
        for (int i = tid; i < 1024; i += NTHR) {
            int bl = i >> 8, k = i & 255;
            s_bc[i] = g_act[(bg * 4 + bl) * ACTDIM + DSSM + k];
        }
        __syncthreads();

        float g = 0.0f;
        if (tid < 256) {
            float x   = g_act[bglb * ACTDIM + h * HEADDIM + dd];
            float dtr = g_act[bglb * ACTDIM + CONVDIM + h];
            float dt  = softplus_f(dtr + dtb);
            float dA  = expf(dt * Ah);
            float coef = dt * x;

            const float* bvp = s_bc + b_loc * 256;
            const float* cvp = bvp + 128;
            float acc = 0.0f;
            int p = tid;
#pragma unroll 4
            for (int n = 0; n < DSTATE; n++) {
                float s = s_state[n * 256 + p];
                s = fmaf(s, dA, coef * bvp[n]);
                acc = fmaf(s, cvp[n], acc);
                s_state[n * 256 + p] = s;
            }
            float y = fmaf(Dh, x, acc);
            float z = g_zxbcdt[(bglb * SEQLEN + t) * DINPROJ + h * HEADDIM + dd];
            g = y * silu_f(z);

            float gsq = g * g;
#pragma unroll
            for (int off = 16; off > 0; off >>= 1)
                gsq += __shfl_xor_sync(0xffffffffu, gsq, off);
            if (lane == 0) s_red[warp] = gsq;   // warps 0..7
        }
        __syncthreads();

        if (tid < 4) {
            float part = s_red[2 * tid] + s_red[2 * tid + 1];
            int slot = t * BATCH + bg * 4 + tid;
            g_mspart[slot * 32 + h] = part;
            __threadfence();
            atomicAdd(&g_mscnt[slot], 1);
            while (*((volatile int*)&g_mscnt[slot]) != 32) { __nanosleep(32); }
            __threadfence();
            float tot = 0.0f;
#pragma unroll 8
            for (int hh = 0; hh < 32; hh++) tot += g_mspart[slot * 32 + hh];
            s_red[8 + tid] = rsqrtf(tot * (1.0f / (float)DSSM) + EPSV);
        }
        __syncthreads();

        if (tid < 256) {
            float r = s_red[8 + b_loc];
            g_yn[bglb * DSSM + h * HEADDIM + dd] = g * r * nw;
        }

        grid_barrier();           // yn(t) visible before phase A(t+1)
    }
}

// ---------------- launcher ----------------
extern "C" void kernel_launch(void* const* d_in, const int* in_sizes, int n_in,
                              void* d_out, int out_size) {
    const float* u       = (const float*)d_in[0];
    const float* W_in    = (const float*)d_in[1];
    const float* conv_w  = (const float*)d_in[2];
    const float* conv_b  = (const float*)d_in[3];
    const float* W_rxbc  = (const float*)d_in[4];
    const float* W_rdt   = (const float*)d_in[5];
    const float* dt_bias = (const float*)d_in[6];
    const float* A_log   = (const float*)d_in[7];
    const float* D_param = (const float*)d_in[8];
    const float* norm_w  = (const float*)d_in[9];
    const float* W_out   = (const float*)d_in[10];
    float* out = (float*)d_out;

    static int smem_set = 0;
    const int SMEM_BYTES = (32768 + 1024 + 16) * 4;
    if (!smem_set) {
        cudaFuncSetAttribute(scan_kernel, cudaFuncAttributeMaxDynamicSharedMemorySize, SMEM_BYTES);
        smem_set = 1;
    }

    dim3 gIn((DINPROJ + 63) / 64, (BATCH * SEQLEN) / 64);
    inproj_kernel<<<gIn, 256>>>(u, W_in);

    int convN = BATCH * SEQLEN * CONVDIM;
    conv_kernel<<<(convN + 255) / 256, 256>>>(conv_w, conv_b);

    scan_kernel<<<NCTA, NTHR, SMEM_BYTES>>>(W_rxbc, W_rdt, dt_bias, A_log,
                                            D_param, norm_w, W_out, out);
}

// round 4
// speedup vs baseline: 1.1821x; 1.1821x over previous
#include <cuda_runtime.h>
#include <math.h>

// ---------------- problem constants ----------------
#define BATCH     16
#define SEQLEN    512
#define DMODEL    1024
#define DSTATE    128
#define DCONV     4
#define HEADDIM   64
#define DSSM      2048
#define NHEADS    32
#define CONVDIM   2304            // DSSM + 2*DSTATE
#define DINPROJ   4384            // 2*DSSM + 2*DSTATE + NHEADS
#define ACTDIM    2336            // CONVDIM + NHEADS
#define NCTA      128
#define NTHR      256
#define EPSV      1e-5f

// SMEM layout (floats)
#define SM_STATE  0                       // 32768
#define SM_Y      32768                   // 2 * 2112 (tile: 16 x 132)
#define SM_BC     (32768 + 4224)          // 1024
#define SM_RED    (32768 + 4224 + 1024)   // 16
#define SM_TOTALF (32768 + 4224 + 1024 + 16)
#define YTILE_STR 132

// ---------------- device scratch ----------------
__device__ float g_zxbcdt[BATCH * SEQLEN * DINPROJ];
__device__ float g_xbcconv[BATCH * SEQLEN * CONVDIM];
__device__ float g_act[BATCH * ACTDIM];
__device__ float g_yn[BATCH * DSSM];
__device__ float g_mspart[SEQLEN * BATCH * 32];
__device__ int   g_mscnt[SEQLEN * BATCH];
__device__ unsigned g_bar_cnt;
__device__ unsigned g_bar_gen;

// ---------------- helpers ----------------
__device__ __forceinline__ float silu_f(float v) { return v / (1.0f + expf(-v)); }
__device__ __forceinline__ float softplus_f(float v) { return (v > 20.0f) ? v : log1pf(expf(v)); }

__device__ __forceinline__ unsigned long long pk2(float lo, float hi) {
    unsigned long long r;
    asm("mov.b64 %0, {%1, %2};" : "=l"(r) : "r"(__float_as_uint(lo)), "r"(__float_as_uint(hi)));
    return r;
}
__device__ __forceinline__ void upk2(unsigned long long v, float& lo, float& hi) {
    unsigned a, b;
    asm("mov.b64 {%0, %1}, %2;" : "=r"(a), "=r"(b) : "l"(v));
    lo = __uint_as_float(a); hi = __uint_as_float(b);
}
__device__ __forceinline__ unsigned long long fma2(unsigned long long a, unsigned long long b,
                                                   unsigned long long c) {
    unsigned long long d;
    asm("fma.rn.f32x2 %0, %1, %2, %3;" : "=l"(d) : "l"(a), "l"(b), "l"(c));
    return d;
}

union F4U { float4 f; unsigned long long u[2]; };

// sense-reversing grid barrier; 128 CTAs co-resident (1 CTA/SM)
__device__ __forceinline__ void grid_barrier() {
    __threadfence();
    __syncthreads();
    if (threadIdx.x == 0) {
        unsigned old = *((volatile unsigned*)&g_bar_gen);
        unsigned a = atomicAdd(&g_bar_cnt, 1u);
        if (a == (unsigned)(NCTA - 1)) {
            atomicExch(&g_bar_cnt, 0u);
            __threadfence();
            atomicAdd(&g_bar_gen, 1u);
        } else {
            while (*((volatile unsigned*)&g_bar_gen) == old) { __nanosleep(64); }
        }
        __threadfence();
    }
    __syncthreads();
}

// ---------------- kernel 1: in_proj GEMM (FFMA2) ----------------
__global__ __launch_bounds__(256) void inproj_kernel(const float* __restrict__ U,
                                                     const float* __restrict__ Win) {
    const int N = DINPROJ;
    const int K = DMODEL;

    __shared__ float As[32][68];    // [k][m]
    __shared__ float Bs[32][68];    // [k][n]

    const int tid   = threadIdx.x;
    const int mbase = blockIdx.y * 64;
    const int nbase = blockIdx.x * 64;
    const int lr = tid >> 3;
    const int lc = (tid & 7) << 2;
    const int ty = tid >> 4;
    const int tx = tid & 15;

    unsigned long long acc2[2][4];
#pragma unroll
    for (int p = 0; p < 2; p++)
#pragma unroll
        for (int j = 0; j < 4; j++) acc2[p][j] = 0ULL;

    for (int k0 = 0; k0 < K; k0 += 32) {
        float4 a0 = *(const float4*)(U + (mbase + lr) * K + k0 + lc);
        float4 a1 = *(const float4*)(U + (mbase + lr + 32) * K + k0 + lc);
        float4 b0 = make_float4(0.f, 0.f, 0.f, 0.f);
        float4 b1 = make_float4(0.f, 0.f, 0.f, 0.f);
        if (nbase + lr < N)      b0 = *(const float4*)(Win + (nbase + lr) * K + k0 + lc);
        if (nbase + lr + 32 < N) b1 = *(const float4*)(Win + (nbase + lr + 32) * K + k0 + lc);

        __syncthreads();
        As[lc + 0][lr] = a0.x; As[lc + 1][lr] = a0.y; As[lc + 2][lr] = a0.z; As[lc + 3][lr] = a0.w;
        As[lc + 0][lr + 32] = a1.x; As[lc + 1][lr + 32] = a1.y; As[lc + 2][lr + 32] = a1.z; As[lc + 3][lr + 32] = a1.w;
        Bs[lc + 0][lr] = b0.x; Bs[lc + 1][lr] = b0.y; Bs[lc + 2][lr] = b0.z; Bs[lc + 3][lr] = b0.w;
        Bs[lc + 0][lr + 32] = b1.x; Bs[lc + 1][lr + 32] = b1.y; Bs[lc + 2][lr + 32] = b1.z; Bs[lc + 3][lr + 32] = b1.w;
        __syncthreads();

#pragma unroll
        for (int kk = 0; kk < 32; kk++) {
            F4U av, bv;
            av.f = *(const float4*)&As[kk][ty * 4];
            bv.f = *(const float4*)&Bs[kk][tx * 4];
            unsigned long long a01 = av.u[0];
            unsigned long long a23 = av.u[1];
            unsigned long long bb0 = pk2(bv.f.x, bv.f.x);
            unsigned long long bb1 = pk2(bv.f.y, bv.f.y);
            unsigned long long bb2 = pk2(bv.f.z, bv.f.z);
            unsigned long long bb3 = pk2(bv.f.w, bv.f.w);
            acc2[0][0] = fma2(a01, bb0, acc2[0][0]);
            acc2[1][0] = fma2(a23, bb0, acc2[1][0]);
            acc2[0][1] = fma2(a01, bb1, acc2[0][1]);
            acc2[1][1] = fma2(a23, bb1, acc2[1][1]);
            acc2[0][2] = fma2(a01, bb2, acc2[0][2]);
            acc2[1][2] = fma2(a23, bb2, acc2[1][2]);
            acc2[0][3] = fma2(a01, bb3, acc2[0][3]);
            acc2[1][3] = fma2(a23, bb3, acc2[1][3]);
        }
    }

#pragma unroll
    for (int p = 0; p < 2; p++) {
#pragma unroll
        for (int j = 0; j < 4; j++) {
            float lo, hi;
            upk2(acc2[p][j], lo, hi);
            int col = nbase + tx * 4 + j;
            if (col < N) {
                g_zxbcdt[(mbase + ty * 4 + 2 * p + 0) * N + col] = lo;
                g_zxbcdt[(mbase + ty * 4 + 2 * p + 1) * N + col] = hi;
            }
        }
    }
}

// ---------------- kernel 2: causal depthwise conv ----------------
__global__ __launch_bounds__(256) void conv_kernel(const float* __restrict__ conv_w,
                                                   const float* __restrict__ conv_b) {
    int idx = blockIdx.x * blockDim.x + threadIdx.x;
    if (idx >= BATCH * SEQLEN * CONVDIM) return;
    int c  = idx % CONVDIM;
    int bt = idx / CONVDIM;
    int t  = bt % SEQLEN;
    int b  = bt / SEQLEN;
    float accv = conv_b[c];
#pragma unroll
    for (int k = 0; k < DCONV; k++) {
        int tt = t + k - (DCONV - 1);
        if (tt >= 0)
            accv = fmaf(g_zxbcdt[(b * SEQLEN + tt) * DINPROJ + DSSM + c],
                        conv_w[c * DCONV + k], accv);
    }
    g_xbcconv[idx] = accv;
}

// ---------------- kernel 3: persistent scan ----------------
// CTA c: head h = c & 31, batch-group bg = c >> 5.
// Phase A: 4 rows/warp, yn staged through SMEM tiles, FFMA2 over col pairs.
__global__ __launch_bounds__(NTHR, 1) void scan_kernel(
    const float* __restrict__ W_rxbc, const float* __restrict__ W_rdt,
    const float* __restrict__ dt_bias, const float* __restrict__ A_log,
    const float* __restrict__ D_param, const float* __restrict__ norm_w,
    const float* __restrict__ W_out, float* __restrict__ out) {

    extern __shared__ float sm[];
    float* s_state = sm + SM_STATE;       // state[n][p], p = b_loc*64+d
    float* s_y     = sm + SM_Y;           // 2 tiles of [16][132]
    float* s_bc    = sm + SM_BC;          // [b_loc][0..127]=Bv, [128..255]=Cv
    float* s_red   = sm + SM_RED;

    const int tid  = threadIdx.x;
    const int cta  = blockIdx.x;
    const int lane = tid & 31;
    const int warp = tid >> 5;

    // per-launch init
    for (int i = cta * NTHR + tid; i < BATCH * DSSM; i += NCTA * NTHR) g_yn[i] = 0.0f;
    for (int i = cta * NTHR + tid; i < SEQLEN * BATCH; i += NCTA * NTHR) g_mscnt[i] = 0;
    for (int i = tid; i < 4 * DSTATE * HEADDIM; i += NTHR) s_state[i] = 0.0f;

    // ---- phase A task setup: 4 rows per warp ----
    const int hasdt = (cta < NHEADS) ? 1 : 0;
    const int ntask = 18 + hasdt + 8;     // 26 or 27
    int typ[4], idx[4];
    bool rv[4];
    const float* wr[4];
    bool any2 = false;
#pragma unroll
    for (int j = 0; j < 4; j++) {
        int r = warp * 4 + j;
        rv[j] = (r < ntask);
        typ[j] = 0; idx[j] = 0; wr[j] = W_rxbc;
        if (rv[j]) {
            if (r < 18) { typ[j] = 0; idx[j] = cta * 18 + r; wr[j] = W_rxbc + idx[j] * DSSM; }
            else {
                r -= 18;
                if (hasdt && r == 0) { typ[j] = 1; idx[j] = cta; wr[j] = W_rdt + cta * DSSM; }
                else { r -= hasdt; typ[j] = 2; idx[j] = cta * 8 + r; wr[j] = W_out + idx[j] * DSSM; }
            }
            if (typ[j] == 2) any2 = true;
        }
    }
    const bool anyrow = rv[0];

    // tile loader mapping
    const int lb = tid >> 4;            // batch 0..15
    const int lcc = (tid & 15) * 8;     // col 0..120

    // ---- phase B constants ----
    const int h  = cta & 31;
    const int bg = cta >> 5;
    const int b_loc = tid >> 6;          // 0..3
    const int dd    = tid & 63;
    const int bglb  = bg * 4 + b_loc;
    const float Ah  = -expf(A_log[h]);
    const float dtb = dt_bias[h];
    const float Dh  = D_param[h];
    const float nw  = norm_w[h * HEADDIM + dd];

    grid_barrier();

    for (int t = 0; t <= SEQLEN; t++) {
        // =================== phase A ===================
        const bool docompute = anyrow && (t < SEQLEN || any2);

        unsigned long long acc[4][16];
#pragma unroll
        for (int j = 0; j < 4; j++)
#pragma unroll
            for (int b = 0; b < 16; b++) acc[j][b] = 0ULL;

        // preload tile 0
        {
            const float* src = g_yn + lb * DSSM + lcc;
            float4 v0 = *(const float4*)(src);
            float4 v1 = *(const float4*)(src + 4);
            float* dst = s_y + lb * YTILE_STR + lcc;
            *(float4*)(dst) = v0;
            *(float4*)(dst + 4) = v1;
        }
        __syncthreads();

        int cur = 0;
        for (int blk = 0; blk < 16; blk++) {
            float4 n0, n1;
            const bool pf = (blk < 15);
            if (pf) {
                const float* src = g_yn + lb * DSSM + (blk + 1) * 128 + lcc;
                n0 = *(const float4*)(src);
                n1 = *(const float4*)(src + 4);
            }

            if (docompute) {
                unsigned long long w01[4], w23[4];
#pragma unroll
                for (int j = 0; j < 4; j++) {
                    F4U wv;
                    wv.f = *(const float4*)(wr[j] + blk * 128 + lane * 4);
                    w01[j] = wv.u[0];
                    w23[j] = wv.u[1];
                }
                const float* yt = s_y + cur * (16 * YTILE_STR) + lane * 4;
#pragma unroll
                for (int b = 0; b < 16; b++) {
                    F4U yv;
                    yv.f = *(const float4*)(yt + b * YTILE_STR);
                    unsigned long long y01 = yv.u[0];
                    unsigned long long y23 = yv.u[1];
#pragma unroll
                    for (int j = 0; j < 4; j++) {
                        acc[j][b] = fma2(w01[j], y01, acc[j][b]);
                        acc[j][b] = fma2(w23[j], y23, acc[j][b]);
                    }
                }
            }

            if (pf) {
                float* dst = s_y + (cur ^ 1) * (16 * YTILE_STR) + lb * YTILE_STR + lcc;
                *(float4*)(dst) = n0;
                *(float4*)(dst + 4) = n1;
            }
            __syncthreads();
            cur ^= 1;
        }

        if (docompute) {
            float outv[4];
#pragma unroll
            for (int j = 0; j < 4; j++) {
                outv[j] = 0.0f;
#pragma unroll
                for (int b = 0; b < 16; b++) {
                    float lo, hi;
                    upk2(acc[j][b], lo, hi);
                    float s = lo + hi;
#pragma unroll
                    for (int off = 16; off > 0; off >>= 1)
                        s += __shfl_xor_sync(0xffffffffu, s, off);
                    if (lane == b) outv[j] = s;
                }
            }

            if (lane < 16) {
                int b = lane;
#pragma unroll
                for (int j = 0; j < 4; j++) {
                    if (!rv[j]) continue;
                    if (typ[j] == 0) {
                        if (t < SEQLEN) {
                            float base = g_xbcconv[(b * SEQLEN + t) * CONVDIM + idx[j]];
                            g_act[b * ACTDIM + idx[j]] = silu_f(base + outv[j]);
                        }
                    } else if (typ[j] == 1) {
                        if (t < SEQLEN) {
                            float base = g_zxbcdt[(b * SEQLEN + t) * DINPROJ + (DSSM + CONVDIM) + idx[j]];
                            g_act[b * ACTDIM + CONVDIM + idx[j]] = silu_f(base + outv[j]);
                        }
                    } else {
                        if (t >= 1) out[(b * SEQLEN + (t - 1)) * DMODEL + idx[j]] = outv[j];
                    }
                }
            }
        }

        if (t == SEQLEN) break;

        grid_barrier();           // act(t) visible

        // =================== phase B ===================
        for (int i = tid; i < 1024; i += NTHR) {
            int bl = i >> 8, k = i & 255;
            s_bc[i] = g_act[(bg * 4 + bl) * ACTDIM + DSSM + k];
        }
        __syncthreads();

        float g = 0.0f;
        {
            float x   = g_act[bglb * ACTDIM + h * HEADDIM + dd];
            float dtr = g_act[bglb * ACTDIM + CONVDIM + h];
            float dt  = softplus_f(dtr + dtb);
            float dA  = expf(dt * Ah);
            float coef = dt * x;

            const float* bvp = s_bc + b_loc * 256;
            const float* cvp = bvp + 128;
            float accv = 0.0f;
            int p = tid;
#pragma unroll 4
            for (int n = 0; n < DSTATE; n++) {
                float s = s_state[n * 256 + p];
                s = fmaf(s, dA, coef * bvp[n]);
                accv = fmaf(s, cvp[n], accv);
                s_state[n * 256 + p] = s;
            }
            float y = fmaf(Dh, x, accv);
            float z = g_zxbcdt[(bglb * SEQLEN + t) * DINPROJ + h * HEADDIM + dd];
            g = y * silu_f(z);

            float gsq = g * g;
#pragma unroll
            for (int off = 16; off > 0; off >>= 1)
                gsq += __shfl_xor_sync(0xffffffffu, gsq, off);
            if (lane == 0) s_red[warp] = gsq;
        }
        __syncthreads();

        if (tid < 4) {
            float part = s_red[2 * tid] + s_red[2 * tid + 1];
            int slot = t * BATCH + bg * 4 + tid;
            g_mspart[slot * 32 + h] = part;
            __threadfence();
            atomicAdd(&g_mscnt[slot], 1);
            while (*((volatile int*)&g_mscnt[slot]) != 32) { __nanosleep(32); }
            __threadfence();
            float tot = 0.0f;
#pragma unroll 8
            for (int hh = 0; hh < 32; hh++) tot += g_mspart[slot * 32 + hh];
            s_red[8 + tid] = rsqrtf(tot * (1.0f / (float)DSSM) + EPSV);
        }
        __syncthreads();

        {
            float r = s_red[8 + b_loc];
            g_yn[bglb * DSSM + h * HEADDIM + dd] = g * r * nw;
        }

        grid_barrier();           // yn(t) visible
    }
}

// ---------------- launcher ----------------
extern "C" void kernel_launch(void* const* d_in, const int* in_sizes, int n_in,
                              void* d_out, int out_size) {
    const float* u       = (const float*)d_in[0];
    const float* W_in    = (const float*)d_in[1];
    const float* conv_w  = (const float*)d_in[2];
    const float* conv_b  = (const float*)d_in[3];
    const float* W_rxbc  = (const float*)d_in[4];
    const float* W_rdt   = (const float*)d_in[5];
    const float* dt_bias = (const float*)d_in[6];
    const float* A_log   = (const float*)d_in[7];
    const float* D_param = (const float*)d_in[8];
    const float* norm_w  = (const float*)d_in[9];
    const float* W_out   = (const float*)d_in[10];
    float* out = (float*)d_out;

    static int smem_set = 0;
    const int SMEM_BYTES = SM_TOTALF * 4;
    if (!smem_set) {
        cudaFuncSetAttribute(scan_kernel, cudaFuncAttributeMaxDynamicSharedMemorySize, SMEM_BYTES);
        smem_set = 1;
    }

    dim3 gIn((DINPROJ + 63) / 64, (BATCH * SEQLEN) / 64);
    inproj_kernel<<<gIn, 256>>>(u, W_in);

    int convN = BATCH * SEQLEN * CONVDIM;
    conv_kernel<<<(convN + 255) / 256, 256>>>(conv_w, conv_b);

    scan_kernel<<<NCTA, NTHR, SMEM_BYTES>>>(W_rxbc, W_rdt, dt_bias, A_log,
                                            D_param, norm_w, W_out, out);
}

// round 6
// speedup vs baseline: 1.2770x; 1.0803x over previous
#include <cuda_runtime.h>
#include <math.h>

// ---------------- problem constants ----------------
#define BATCH     16
#define SEQLEN    512
#define DMODEL    1024
#define DSTATE    128
#define DCONV     4
#define HEADDIM   64
#define DSSM      2048
#define NHEADS    32
#define CONVDIM   2304            // DSSM + 2*DSTATE
#define DINPROJ   4384            // 2*DSSM + 2*DSTATE + NHEADS
#define ACTDIM    2336            // CONVDIM + NHEADS
#define NCTA      128
#define NTHR      256
#define EPSV      1e-5f

// SMEM layout (floats)
#define SM_STATE  0                       // 32768
#define SM_Y      32768                   // 2 * 2112 (tile: 16 x 132)
#define SM_BC     (32768 + 4224)          // 1024
#define SM_RED    (32768 + 4224 + 1024)   // 32
#define SM_TOTALF (32768 + 4224 + 1024 + 32)
#define YTILE_STR 132

// ---------------- device scratch ----------------
__device__ float g_zxbcdt[BATCH * SEQLEN * DINPROJ];
__device__ float g_xbcconv[BATCH * SEQLEN * CONVDIM];
__device__ float g_act[BATCH * ACTDIM];
__device__ float g_yn[BATCH * DSSM];            // UN-normalized g*norm_w (r deferred)
__device__ float g_mspart[BATCH * 32];          // per (batch, head) sum of g^2
__device__ unsigned g_arrive[NCTA * 32];        // padded per-CTA epoch flags (monotonic)
__device__ unsigned g_release;                  // master release word (monotonic)

// ---------------- helpers ----------------
__device__ __forceinline__ float silu_f(float v) { return v / (1.0f + expf(-v)); }
__device__ __forceinline__ float softplus_f(float v) { return (v > 20.0f) ? v : log1pf(expf(v)); }

__device__ __forceinline__ void upk2(unsigned long long v, float& lo, float& hi) {
    unsigned a, b;
    asm("mov.b64 {%0, %1}, %2;" : "=r"(a), "=r"(b) : "l"(v));
    lo = __uint_as_float(a); hi = __uint_as_float(b);
}
__device__ __forceinline__ unsigned long long pk2(float lo, float hi) {
    unsigned long long r;
    asm("mov.b64 %0, {%1, %2};" : "=l"(r) : "r"(__float_as_uint(lo)), "r"(__float_as_uint(hi)));
    return r;
}
__device__ __forceinline__ unsigned long long fma2(unsigned long long a, unsigned long long b,
                                                   unsigned long long c) {
    unsigned long long d;
    asm("fma.rn.f32x2 %0, %1, %2, %3;" : "=l"(d) : "l"(a), "l"(b), "l"(c));
    return d;
}

union F4U { float4 f; unsigned long long u[2]; };

// flag-based grid barrier with R4's proven fence discipline:
// every thread __threadfence()s its own stores (gpu scope -> visible + L1 flushed),
// bar.sync joins, tid0 publishes the epoch with a volatile store.
__device__ __forceinline__ void grid_barrier(int cta, unsigned epoch) {
    __threadfence();
    __syncthreads();
    if (threadIdx.x == 0) *(volatile unsigned*)&g_arrive[cta * 32] = epoch;
    if (cta == 0) {
        if (threadIdx.x < 128) {
            while (*(volatile unsigned*)&g_arrive[threadIdx.x * 32] < epoch) { __nanosleep(32); }
        }
        __syncthreads();
        if (threadIdx.x == 0) {
            __threadfence();
            *(volatile unsigned*)&g_release = epoch;
        }
    } else {
        if (threadIdx.x == 0) {
            while (*(volatile unsigned*)&g_release < epoch) { __nanosleep(32); }
        }
    }
    __syncthreads();
}

// ---------------- kernel 1: in_proj GEMM (FFMA2) ----------------
__global__ __launch_bounds__(256) void inproj_kernel(const float* __restrict__ U,
                                                     const float* __restrict__ Win) {
    const int N = DINPROJ;
    const int K = DMODEL;

    __shared__ float As[32][68];
    __shared__ float Bs[32][68];

    const int tid   = threadIdx.x;
    const int mbase = blockIdx.y * 64;
    const int nbase = blockIdx.x * 64;
    const int lr = tid >> 3;
    const int lc = (tid & 7) << 2;
    const int ty = tid >> 4;
    const int tx = tid & 15;

    unsigned long long acc2[2][4];
#pragma unroll
    for (int p = 0; p < 2; p++)
#pragma unroll
        for (int j = 0; j < 4; j++) acc2[p][j] = 0ULL;

    for (int k0 = 0; k0 < K; k0 += 32) {
        float4 a0 = *(const float4*)(U + (mbase + lr) * K + k0 + lc);
        float4 a1 = *(const float4*)(U + (mbase + lr + 32) * K + k0 + lc);
        float4 b0 = make_float4(0.f, 0.f, 0.f, 0.f);
        float4 b1 = make_float4(0.f, 0.f, 0.f, 0.f);
        if (nbase + lr < N)      b0 = *(const float4*)(Win + (nbase + lr) * K + k0 + lc);
        if (nbase + lr + 32 < N) b1 = *(const float4*)(Win + (nbase + lr + 32) * K + k0 + lc);

        __syncthreads();
        As[lc + 0][lr] = a0.x; As[lc + 1][lr] = a0.y; As[lc + 2][lr] = a0.z; As[lc + 3][lr] = a0.w;
        As[lc + 0][lr + 32] = a1.x; As[lc + 1][lr + 32] = a1.y; As[lc + 2][lr + 32] = a1.z; As[lc + 3][lr + 32] = a1.w;
        Bs[lc + 0][lr] = b0.x; Bs[lc + 1][lr] = b0.y; Bs[lc + 2][lr] = b0.z; Bs[lc + 3][lr] = b0.w;
        Bs[lc + 0][lr + 32] = b1.x; Bs[lc + 1][lr + 32] = b1.y; Bs[lc + 2][lr + 32] = b1.z; Bs[lc + 3][lr + 32] = b1.w;
        __syncthreads();

#pragma unroll
        for (int kk = 0; kk < 32; kk++) {
            F4U av, bv;
            av.f = *(const float4*)&As[kk][ty * 4];
            bv.f = *(const float4*)&Bs[kk][tx * 4];
            unsigned long long a01 = av.u[0];
            unsigned long long a23 = av.u[1];
            unsigned long long bb0 = pk2(bv.f.x, bv.f.x);
            unsigned long long bb1 = pk2(bv.f.y, bv.f.y);
            unsigned long long bb2 = pk2(bv.f.z, bv.f.z);
            unsigned long long bb3 = pk2(bv.f.w, bv.f.w);
            acc2[0][0] = fma2(a01, bb0, acc2[0][0]);
            acc2[1][0] = fma2(a23, bb0, acc2[1][0]);
            acc2[0][1] = fma2(a01, bb1, acc2[0][1]);
            acc2[1][1] = fma2(a23, bb1, acc2[1][1]);
            acc2[0][2] = fma2(a01, bb2, acc2[0][2]);
            acc2[1][2] = fma2(a23, bb2, acc2[1][2]);
            acc2[0][3] = fma2(a01, bb3, acc2[0][3]);
            acc2[1][3] = fma2(a23, bb3, acc2[1][3]);
        }
    }

#pragma unroll
    for (int p = 0; p < 2; p++) {
#pragma unroll
        for (int j = 0; j < 4; j++) {
            float lo, hi;
            upk2(acc2[p][j], lo, hi);
            int col = nbase + tx * 4 + j;
            if (col < N) {
                g_zxbcdt[(mbase + ty * 4 + 2 * p + 0) * N + col] = lo;
                g_zxbcdt[(mbase + ty * 4 + 2 * p + 1) * N + col] = hi;
            }
        }
    }
}

// ---------------- kernel 2: causal depthwise conv ----------------
__global__ __launch_bounds__(256) void conv_kernel(const float* __restrict__ conv_w,
                                                   const float* __restrict__ conv_b) {
    int idx = blockIdx.x * blockDim.x + threadIdx.x;
    if (idx >= BATCH * SEQLEN * CONVDIM) return;
    int c  = idx % CONVDIM;
    int bt = idx / CONVDIM;
    int t  = bt % SEQLEN;
    int b  = bt / SEQLEN;
    float accv = conv_b[c];
#pragma unroll
    for (int k = 0; k < DCONV; k++) {
        int tt = t + k - (DCONV - 1);
        if (tt >= 0)
            accv = fmaf(g_zxbcdt[(b * SEQLEN + tt) * DINPROJ + DSSM + c],
                        conv_w[c * DCONV + k], accv);
    }
    g_xbcconv[idx] = accv;
}

// ---------------- kernel 3: persistent scan ----------------
// CTA c: head h = c & 31, batch-group bg = c >> 5.
// g_yn holds UN-normalized g*norm_w; the per-batch scalar rsqrt factor is applied
// in phase A (linearity of the dot products). This removes the per-step RMS sync.
__global__ __launch_bounds__(NTHR, 1) void scan_kernel(
    const float* __restrict__ W_rxbc, const float* __restrict__ W_rdt,
    const float* __restrict__ dt_bias, const float* __restrict__ A_log,
    const float* __restrict__ D_param, const float* __restrict__ norm_w,
    const float* __restrict__ W_out, float* __restrict__ out) {

    extern __shared__ float sm[];
    float* s_state = sm + SM_STATE;       // state[n][p], p = b_loc*64+d
    float* s_y     = sm + SM_Y;           // 2 tiles of [16][132]
    float* s_bc    = sm + SM_BC;          // [b_loc][0..127]=Bv, [128..255]=Cv
    float* s_red   = sm + SM_RED;         // [0..15]=r per batch, [16..23]=warp partials
    __shared__ unsigned s_base;

    const int tid  = threadIdx.x;
    const int cta  = blockIdx.x;
    const int lane = tid & 31;
    const int warp = tid >> 5;

    // epoch base: monotonic across graph replays (previous launch fully completed)
    if (tid == 0) s_base = *(volatile unsigned*)&g_release;
    // per-launch init
    for (int i = cta * NTHR + tid; i < BATCH * DSSM; i += NCTA * NTHR) g_yn[i] = 0.0f;
    for (int i = tid; i < 4 * DSTATE * HEADDIM; i += NTHR) s_state[i] = 0.0f;
    __syncthreads();
    unsigned epoch = s_base + 1;

    // ---- phase A task setup: 4 rows per warp ----
    const int hasdt = (cta < NHEADS) ? 1 : 0;
    const int ntask = 18 + hasdt + 8;
    int typ[4], idx[4];
    bool rv[4];
    const float* wr[4];
    bool any2 = false;
#pragma unroll
    for (int j = 0; j < 4; j++) {
        int r = warp * 4 + j;
        rv[j] = (r < ntask);
        typ[j] = 0; idx[j] = 0; wr[j] = W_rxbc;
        if (rv[j]) {
            if (r < 18) { typ[j] = 0; idx[j] = cta * 18 + r; wr[j] = W_rxbc + idx[j] * DSSM; }
            else {
                r -= 18;
                if (hasdt && r == 0) { typ[j] = 1; idx[j] = cta; wr[j] = W_rdt + cta * DSSM; }
                else { r -= hasdt; typ[j] = 2; idx[j] = cta * 8 + r; wr[j] = W_out + idx[j] * DSSM; }
            }
            if (typ[j] == 2) any2 = true;
        }
    }
    const bool anyrow = rv[0];

    const int lb = tid >> 4;            // batch 0..15 (y tile loader)
    const int lcc = (tid & 15) * 8;     // col 0..120

    // ---- phase B constants ----
    const int h  = cta & 31;
    const int bg = cta >> 5;
    const int b_loc = tid >> 6;
    const int dd    = tid & 63;
    const int bglb  = bg * 4 + b_loc;
    const float Ah  = -expf(A_log[h]);
    const float dtb = dt_bias[h];
    const float Dh  = D_param[h];
    const float nw  = norm_w[h * HEADDIM + dd];

    grid_barrier(cta, epoch++);   // init (g_yn zeros) visible everywhere

    for (int t = 0; t <= SEQLEN; t++) {
        // =================== phase A ===================
        const bool docompute = anyrow && (t < SEQLEN || any2);

        // per-batch rsqrt factors from last step's partials (t=0: dots are 0 anyway)
        if (tid < 16) {
            const float* mp = g_mspart + tid * 32;
            float tot = 0.0f;
#pragma unroll
            for (int q = 0; q < 8; q++) {
                float4 v = *(const float4*)(mp + q * 4);
                tot += v.x + v.y + v.z + v.w;
            }
            s_red[tid] = rsqrtf(tot * (1.0f / (float)DSSM) + EPSV);
        }

        unsigned long long acc[4][16];
#pragma unroll
        for (int j = 0; j < 4; j++)
#pragma unroll
            for (int b = 0; b < 16; b++) acc[j][b] = 0ULL;

        // preload y tile 0 + weight blk 0
        {
            const float* src = g_yn + lb * DSSM + lcc;
            float4 v0 = *(const float4*)(src);
            float4 v1 = *(const float4*)(src + 4);
            float* dst = s_y + lb * YTILE_STR + lcc;
            *(float4*)(dst) = v0;
            *(float4*)(dst + 4) = v1;
        }
        F4U wcur[4];
#pragma unroll
        for (int j = 0; j < 4; j++)
            wcur[j].f = *(const float4*)(wr[j] + lane * 4);
        __syncthreads();

        int cur = 0;
        for (int blk = 0; blk < 16; blk++) {
            float4 n0, n1;
            const bool pf = (blk < 15);
            if (pf) {
                const float* src = g_yn + lb * DSSM + (blk + 1) * 128 + lcc;
                n0 = *(const float4*)(src);
                n1 = *(const float4*)(src + 4);
            }
            F4U wnext[4];
            if (pf) {
#pragma unroll
                for (int j = 0; j < 4; j++)
                    wnext[j].f = *(const float4*)(wr[j] + (blk + 1) * 128 + lane * 4);
            }

            if (docompute) {
                unsigned long long w01[4], w23[4];
#pragma unroll
                for (int j = 0; j < 4; j++) { w01[j] = wcur[j].u[0]; w23[j] = wcur[j].u[1]; }
                const float* yt = s_y + cur * (16 * YTILE_STR) + lane * 4;
#pragma unroll
                for (int b = 0; b < 16; b++) {
                    F4U yv;
                    yv.f = *(const float4*)(yt + b * YTILE_STR);
                    unsigned long long y01 = yv.u[0];
                    unsigned long long y23 = yv.u[1];
#pragma unroll
                    for (int j = 0; j < 4; j++) {
                        acc[j][b] = fma2(w01[j], y01, acc[j][b]);
                        acc[j][b] = fma2(w23[j], y23, acc[j][b]);
                    }
                }
            }

            if (pf) {
                float* dst = s_y + (cur ^ 1) * (16 * YTILE_STR) + lb * YTILE_STR + lcc;
                *(float4*)(dst) = n0;
                *(float4*)(dst + 4) = n1;
#pragma unroll
                for (int j = 0; j < 4; j++) wcur[j] = wnext[j];
            }
            __syncthreads();
            cur ^= 1;
        }

        if (docompute) {
            float outv[4];
#pragma unroll
            for (int j = 0; j < 4; j++) {
                outv[j] = 0.0f;
#pragma unroll
                for (int b = 0; b < 16; b++) {
                    float lo, hi;
                    upk2(acc[j][b], lo, hi);
                    float s = lo + hi;
#pragma unroll
                    for (int off = 16; off > 0; off >>= 1)
                        s += __shfl_xor_sync(0xffffffffu, s, off);
                    if (lane == b) outv[j] = s;
                }
            }

            if (lane < 16) {
                int b = lane;
                float rb = s_red[b];   // scalar rsqrt factor for this batch
#pragma unroll
                for (int j = 0; j < 4; j++) {
                    if (!rv[j]) continue;
                    float val = outv[j] * rb;
                    if (typ[j] == 0) {
                        if (t < SEQLEN) {
                            float base = g_xbcconv[(b * SEQLEN + t) * CONVDIM + idx[j]];
                            g_act[b * ACTDIM + idx[j]] = silu_f(base + val);
                        }
                    } else if (typ[j] == 1) {
                        if (t < SEQLEN) {
                            float base = g_zxbcdt[(b * SEQLEN + t) * DINPROJ + (DSSM + CONVDIM) + idx[j]];
                            g_act[b * ACTDIM + CONVDIM + idx[j]] = silu_f(base + val);
                        }
                    } else {
                        if (t >= 1) out[(b * SEQLEN + (t - 1)) * DMODEL + idx[j]] = val;
                    }
                }
            }
        }

        if (t == SEQLEN) break;

        grid_barrier(cta, epoch++);   // act(t) visible

        // =================== phase B ===================
        for (int i = tid; i < 1024; i += NTHR) {
            int bl = i >> 8, k = i & 255;
            s_bc[i] = g_act[(bg * 4 + bl) * ACTDIM + DSSM + k];
        }
        __syncthreads();

        {
            float x   = g_act[bglb * ACTDIM + h * HEADDIM + dd];
            float dtr = g_act[bglb * ACTDIM + CONVDIM + h];
            float dt  = softplus_f(dtr + dtb);
            float dA  = expf(dt * Ah);
            float coef = dt * x;

            const float* bvp = s_bc + b_loc * 256;
            const float* cvp = bvp + 128;
            float accv = 0.0f;
            int p = tid;
#pragma unroll 4
            for (int n = 0; n < DSTATE; n++) {
                float s = s_state[n * 256 + p];
                s = fmaf(s, dA, coef * bvp[n]);
                accv = fmaf(s, cvp[n], accv);
                s_state[n * 256 + p] = s;
            }
            float y = fmaf(Dh, x, accv);
            float z = g_zxbcdt[(bglb * SEQLEN + t) * DINPROJ + h * HEADDIM + dd];
            float g = y * silu_f(z);

            // write un-normalized g * norm_w; r deferred to phase A
            g_yn[bglb * DSSM + h * HEADDIM + dd] = g * nw;

            // per-(batch, head) partial sum of g^2 (pre-norm_w, per reference)
            float gsq = g * g;
#pragma unroll
            for (int off = 16; off > 0; off >>= 1)
                gsq += __shfl_xor_sync(0xffffffffu, gsq, off);
            if (lane == 0) s_red[16 + warp] = gsq;
        }
        __syncthreads();

        if (tid < 4) {
            float part = s_red[16 + 2 * tid] + s_red[16 + 2 * tid + 1];
            g_mspart[(bg * 4 + tid) * 32 + h] = part;
        }

        grid_barrier(cta, epoch++);   // yn(t) + partials visible
    }
}

// ---------------- launcher ----------------
extern "C" void kernel_launch(void* const* d_in, const int* in_sizes, int n_in,
                              void* d_out, int out_size) {
    const float* u       = (const float*)d_in[0];
    const float* W_in    = (const float*)d_in[1];
    const float* conv_w  = (const float*)d_in[2];
    const float* conv_b  = (const float*)d_in[3];
    const float* W_rxbc  = (const float*)d_in[4];
    const float* W_rdt   = (const float*)d_in[5];
    const float* dt_bias = (const float*)d_in[6];
    const float* A_log   = (const float*)d_in[7];
    const float* D_param = (const float*)d_in[8];
    const float* norm_w  = (const float*)d_in[9];
    const float* W_out   = (const float*)d_in[10];
    float* out = (float*)d_out;

    static int smem_set = 0;
    const int SMEM_BYTES = SM_TOTALF * 4;
    if (!smem_set) {
        cudaFuncSetAttribute(scan_kernel, cudaFuncAttributeMaxDynamicSharedMemorySize, SMEM_BYTES);
        smem_set = 1;
    }

    dim3 gIn((DINPROJ + 63) / 64, (BATCH * SEQLEN) / 64);
    inproj_kernel<<<gIn, 256>>>(u, W_in);

    int convN = BATCH * SEQLEN * CONVDIM;
    conv_kernel<<<(convN + 255) / 256, 256>>>(conv_w, conv_b);

    scan_kernel<<<NCTA, NTHR, SMEM_BYTES>>>(W_rxbc, W_rdt, dt_bias, A_log,
                                            D_param, norm_w, W_out, out);
}

// round 7
// speedup vs baseline: 1.3824x; 1.0825x over previous
#include <cuda_runtime.h>
#include <math.h>

// ---------------- problem constants ----------------
#define BATCH     16
#define SEQLEN    512
#define DMODEL    1024
#define DSTATE    128
#define DCONV     4
#define HEADDIM   64
#define DSSM      2048
#define NHEADS    32
#define CONVDIM   2304            // DSSM + 2*DSTATE
#define DINPROJ   4384            // 2*DSSM + 2*DSTATE + NHEADS
#define ACTDIM    2336            // CONVDIM + NHEADS
#define NCTA      128
#define NTHR      256
#define EPSV      1e-5f

// SMEM layout (floats)
#define SM_STATE  0                       // 32768
#define SM_Y      32768                   // 2 * 2112 (tile: 16 x 132)
#define SM_BC     (32768 + 4224)          // 1024
#define SM_RED    (32768 + 4224 + 1024)   // 32
#define SM_TOTALF (32768 + 4224 + 1024 + 32)
#define YTILE_STR 132

// ---------------- device scratch ----------------
__device__ float g_zxbcdt[BATCH * SEQLEN * DINPROJ];
__device__ float g_xbcconv[BATCH * SEQLEN * CONVDIM];
__device__ float g_act[BATCH * ACTDIM];
__device__ float g_yn[BATCH * DSSM];            // UN-normalized g*norm_w (r deferred)
__device__ float g_mspart[BATCH * 32];          // per (batch, head) sum of g^2
__device__ unsigned g_arrive[NCTA * 32];        // padded per-CTA epoch flags (monotonic)
__device__ unsigned g_release;                  // master release word (monotonic)

// ---------------- helpers ----------------
__device__ __forceinline__ float silu_f(float v) { return v / (1.0f + expf(-v)); }
__device__ __forceinline__ float softplus_f(float v) { return (v > 20.0f) ? v : log1pf(expf(v)); }

__device__ __forceinline__ void upk2(unsigned long long v, float& lo, float& hi) {
    unsigned a, b;
    asm("mov.b64 {%0, %1}, %2;" : "=r"(a), "=r"(b) : "l"(v));
    lo = __uint_as_float(a); hi = __uint_as_float(b);
}
__device__ __forceinline__ unsigned long long pk2(float lo, float hi) {
    unsigned long long r;
    asm("mov.b64 %0, {%1, %2};" : "=l"(r) : "r"(__float_as_uint(lo)), "r"(__float_as_uint(hi)));
    return r;
}
__device__ __forceinline__ unsigned long long fma2(unsigned long long a, unsigned long long b,
                                                   unsigned long long c) {
    unsigned long long d;
    asm("fma.rn.f32x2 %0, %1, %2, %3;" : "=l"(d) : "l"(a), "l"(b), "l"(c));
    return d;
}

// ---- strong (L2-coherent) memory ops: no fences, no L1 flush ----
__device__ __forceinline__ void st_release_u(unsigned* p, unsigned v) {
    asm volatile("st.release.gpu.global.u32 [%0], %1;" :: "l"(p), "r"(v) : "memory");
}
__device__ __forceinline__ unsigned ld_acquire_u(const unsigned* p) {
    unsigned v;
    asm volatile("ld.acquire.gpu.global.u32 %0, [%1];" : "=r"(v) : "l"(p) : "memory");
    return v;
}
__device__ __forceinline__ float ld_rlx_f(const float* p) {
    float v;
    asm volatile("ld.relaxed.gpu.global.f32 %0, [%1];" : "=f"(v) : "l"(p) : "memory");
    return v;
}
__device__ __forceinline__ void st_rlx_f(float* p, float v) {
    asm volatile("st.relaxed.gpu.global.f32 [%0], %1;" :: "l"(p), "f"(v) : "memory");
}
__device__ __forceinline__ float4 ld_rlx_f4(const float* p) {
    float4 v;
    asm volatile("ld.relaxed.gpu.global.v4.f32 {%0,%1,%2,%3}, [%4];"
                 : "=f"(v.x), "=f"(v.y), "=f"(v.z), "=f"(v.w) : "l"(p) : "memory");
    return v;
}

union F4U { float4 f; unsigned long long u[2]; };

// Flag-based grid barrier (hot spin, no fences, no nanosleep).
// Correctness: mutable data uses strong relaxed ops; bar.sync gives intra-CTA
// happens-before; tid0's st.release carries all of it; pollers use ld.acquire.
__device__ __forceinline__ void grid_barrier(int cta, unsigned epoch) {
    __syncthreads();
    if (threadIdx.x == 0) st_release_u(&g_arrive[cta * 32], epoch);
    if (cta == 0) {
        if (threadIdx.x < 128) {
            while (ld_acquire_u(&g_arrive[threadIdx.x * 32]) < epoch) { }
        }
        __syncthreads();
        if (threadIdx.x == 0) st_release_u(&g_release, epoch);
    } else {
        if (threadIdx.x == 0) {
            while (ld_acquire_u(&g_release) < epoch) { }
        }
    }
    __syncthreads();
}

// ---------------- kernel 1: in_proj GEMM (FFMA2) ----------------
__global__ __launch_bounds__(256) void inproj_kernel(const float* __restrict__ U,
                                                     const float* __restrict__ Win) {
    const int N = DINPROJ;
    const int K = DMODEL;

    __shared__ float As[32][68];
    __shared__ float Bs[32][68];

    const int tid   = threadIdx.x;
    const int mbase = blockIdx.y * 64;
    const int nbase = blockIdx.x * 64;
    const int lr = tid >> 3;
    const int lc = (tid & 7) << 2;
    const int ty = tid >> 4;
    const int tx = tid & 15;

    unsigned long long acc2[2][4];
#pragma unroll
    for (int p = 0; p < 2; p++)
#pragma unroll
        for (int j = 0; j < 4; j++) acc2[p][j] = 0ULL;

    for (int k0 = 0; k0 < K; k0 += 32) {
        float4 a0 = *(const float4*)(U + (mbase + lr) * K + k0 + lc);
        float4 a1 = *(const float4*)(U + (mbase + lr + 32) * K + k0 + lc);
        float4 b0 = make_float4(0.f, 0.f, 0.f, 0.f);
        float4 b1 = make_float4(0.f, 0.f, 0.f, 0.f);
        if (nbase + lr < N)      b0 = *(const float4*)(Win + (nbase + lr) * K + k0 + lc);
        if (nbase + lr + 32 < N) b1 = *(const float4*)(Win + (nbase + lr + 32) * K + k0 + lc);

        __syncthreads();
        As[lc + 0][lr] = a0.x; As[lc + 1][lr] = a0.y; As[lc + 2][lr] = a0.z; As[lc + 3][lr] = a0.w;
        As[lc + 0][lr + 32] = a1.x; As[lc + 1][lr + 32] = a1.y; As[lc + 2][lr + 32] = a1.z; As[lc + 3][lr + 32] = a1.w;
        Bs[lc + 0][lr] = b0.x; Bs[lc + 1][lr] = b0.y; Bs[lc + 2][lr] = b0.z; Bs[lc + 3][lr] = b0.w;
        Bs[lc + 0][lr + 32] = b1.x; Bs[lc + 1][lr + 32] = b1.y; Bs[lc + 2][lr + 32] = b1.z; Bs[lc + 3][lr + 32] = b1.w;
        __syncthreads();

#pragma unroll
        for (int kk = 0; kk < 32; kk++) {
            F4U av, bv;
            av.f = *(const float4*)&As[kk][ty * 4];
            bv.f = *(const float4*)&Bs[kk][tx * 4];
            unsigned long long a01 = av.u[0];
            unsigned long long a23 = av.u[1];
            unsigned long long bb0 = pk2(bv.f.x, bv.f.x);
            unsigned long long bb1 = pk2(bv.f.y, bv.f.y);
            unsigned long long bb2 = pk2(bv.f.z, bv.f.z);
            unsigned long long bb3 = pk2(bv.f.w, bv.f.w);
            acc2[0][0] = fma2(a01, bb0, acc2[0][0]);
            acc2[1][0] = fma2(a23, bb0, acc2[1][0]);
            acc2[0][1] = fma2(a01, bb1, acc2[0][1]);
            acc2[1][1] = fma2(a23, bb1, acc2[1][1]);
            acc2[0][2] = fma2(a01, bb2, acc2[0][2]);
            acc2[1][2] = fma2(a23, bb2, acc2[1][2]);
            acc2[0][3] = fma2(a01, bb3, acc2[0][3]);
            acc2[1][3] = fma2(a23, bb3, acc2[1][3]);
        }
    }

#pragma unroll
    for (int p = 0; p < 2; p++) {
#pragma unroll
        for (int j = 0; j < 4; j++) {
            float lo, hi;
            upk2(acc2[p][j], lo, hi);
            int col = nbase + tx * 4 + j;
            if (col < N) {
                g_zxbcdt[(mbase + ty * 4 + 2 * p + 0) * N + col] = lo;
                g_zxbcdt[(mbase + ty * 4 + 2 * p + 1) * N + col] = hi;
            }
        }
    }
}

// ---------------- kernel 2: causal depthwise conv ----------------
__global__ __launch_bounds__(256) void conv_kernel(const float* __restrict__ conv_w,
                                                   const float* __restrict__ conv_b) {
    int idx = blockIdx.x * blockDim.x + threadIdx.x;
    if (idx >= BATCH * SEQLEN * CONVDIM) return;
    int c  = idx % CONVDIM;
    int bt = idx / CONVDIM;
    int t  = bt % SEQLEN;
    int b  = bt / SEQLEN;
    float accv = conv_b[c];
#pragma unroll
    for (int k = 0; k < DCONV; k++) {
        int tt = t + k - (DCONV - 1);
        if (tt >= 0)
            accv = fmaf(g_zxbcdt[(b * SEQLEN + tt) * DINPROJ + DSSM + c],
                        conv_w[c * DCONV + k], accv);
    }
    g_xbcconv[idx] = accv;
}

// ---------------- kernel 3: persistent scan ----------------
// CTA c: head h = c & 31, batch-group bg = c >> 5.
// g_yn holds UN-normalized g*norm_w; per-batch rsqrt factor applied in phase A.
__global__ __launch_bounds__(NTHR, 1) void scan_kernel(
    const float* __restrict__ W_rxbc, const float* __restrict__ W_rdt,
    const float* __restrict__ dt_bias, const float* __restrict__ A_log,
    const float* __restrict__ D_param, const float* __restrict__ norm_w,
    const float* __restrict__ W_out, float* __restrict__ out) {

    extern __shared__ float sm[];
    float* s_state = sm + SM_STATE;       // state[n][p], p = b_loc*64+d
    float* s_y     = sm + SM_Y;           // 2 tiles of [16][132]
    float* s_bc    = sm + SM_BC;          // [b_loc][0..127]=Bv, [128..255]=Cv
    float* s_red   = sm + SM_RED;         // [0..15]=r per batch, [16..23]=warp partials
    __shared__ unsigned s_base;

    const int tid  = threadIdx.x;
    const int cta  = blockIdx.x;
    const int lane = tid & 31;
    const int warp = tid >> 5;

    // epoch base: monotonic across graph replays
    if (tid == 0) s_base = ld_acquire_u(&g_release);
    // per-launch init
    for (int i = cta * NTHR + tid; i < BATCH * DSSM; i += NCTA * NTHR) st_rlx_f(&g_yn[i], 0.0f);
    for (int i = tid; i < 4 * DSTATE * HEADDIM; i += NTHR) s_state[i] = 0.0f;
    __syncthreads();
    unsigned epoch = s_base + 1;

    // ---- phase A task setup: 4 rows per warp ----
    const int hasdt = (cta < NHEADS) ? 1 : 0;
    const int ntask = 18 + hasdt + 8;
    int typ[4], idx[4];
    bool rv[4];
    const float* wr[4];
    bool any2 = false;
#pragma unroll
    for (int j = 0; j < 4; j++) {
        int r = warp * 4 + j;
        rv[j] = (r < ntask);
        typ[j] = 0; idx[j] = 0; wr[j] = W_rxbc;
        if (rv[j]) {
            if (r < 18) { typ[j] = 0; idx[j] = cta * 18 + r; wr[j] = W_rxbc + idx[j] * DSSM; }
            else {
                r -= 18;
                if (hasdt && r == 0) { typ[j] = 1; idx[j] = cta; wr[j] = W_rdt + cta * DSSM; }
                else { r -= hasdt; typ[j] = 2; idx[j] = cta * 8 + r; wr[j] = W_out + idx[j] * DSSM; }
            }
            if (typ[j] == 2) any2 = true;
        }
    }
    const bool anyrow = rv[0];

    const int lb = tid >> 4;            // batch 0..15 (y tile loader)
    const int lcc = (tid & 15) * 8;     // col 0..120

    // ---- phase B constants ----
    const int h  = cta & 31;
    const int bg = cta >> 5;
    const int b_loc = tid >> 6;
    const int dd    = tid & 63;
    const int bglb  = bg * 4 + b_loc;
    const float Ah  = -expf(A_log[h]);
    const float dtb = dt_bias[h];
    const float Dh  = D_param[h];
    const float nw  = norm_w[h * HEADDIM + dd];

    grid_barrier(cta, epoch++);   // init (g_yn zeros) visible everywhere

    for (int t = 0; t <= SEQLEN; t++) {
        // =================== phase A ===================
        const bool docompute = anyrow && (t < SEQLEN || any2);

        // per-batch rsqrt factors from last step's partials (t=0: dots are 0 anyway)
        if (tid < 16) {
            const float* mp = g_mspart + tid * 32;
            float tot = 0.0f;
#pragma unroll
            for (int q = 0; q < 8; q++) {
                float4 v = ld_rlx_f4(mp + q * 4);
                tot += v.x + v.y + v.z + v.w;
            }
            s_red[tid] = rsqrtf(tot * (1.0f / (float)DSSM) + EPSV);
        }

        unsigned long long acc[4][16];
#pragma unroll
        for (int j = 0; j < 4; j++)
#pragma unroll
            for (int b = 0; b < 16; b++) acc[j][b] = 0ULL;

        // preload y tile 0 + weight blk 0
        {
            const float* src = g_yn + lb * DSSM + lcc;
            float4 v0 = ld_rlx_f4(src);
            float4 v1 = ld_rlx_f4(src + 4);
            float* dst = s_y + lb * YTILE_STR + lcc;
            *(float4*)(dst) = v0;
            *(float4*)(dst + 4) = v1;
        }
        F4U wcur[4];
#pragma unroll
        for (int j = 0; j < 4; j++)
            wcur[j].f = *(const float4*)(wr[j] + lane * 4);
        __syncthreads();

        int cur = 0;
        for (int blk = 0; blk < 16; blk++) {
            float4 n0, n1;
            const bool pf = (blk < 15);
            if (pf) {
                const float* src = g_yn + lb * DSSM + (blk + 1) * 128 + lcc;
                n0 = ld_rlx_f4(src);
                n1 = ld_rlx_f4(src + 4);
            }
            F4U wnext[4];
            if (pf) {
#pragma unroll
                for (int j = 0; j < 4; j++)
                    wnext[j].f = *(const float4*)(wr[j] + (blk + 1) * 128 + lane * 4);
            }

            if (docompute) {
                unsigned long long w01[4], w23[4];
#pragma unroll
                for (int j = 0; j < 4; j++) { w01[j] = wcur[j].u[0]; w23[j] = wcur[j].u[1]; }
                const float* yt = s_y + cur * (16 * YTILE_STR) + lane * 4;
#pragma unroll
                for (int b = 0; b < 16; b++) {
                    F4U yv;
                    yv.f = *(const float4*)(yt + b * YTILE_STR);
                    unsigned long long y01 = yv.u[0];
                    unsigned long long y23 = yv.u[1];
#pragma unroll
                    for (int j = 0; j < 4; j++) {
                        acc[j][b] = fma2(w01[j], y01, acc[j][b]);
                        acc[j][b] = fma2(w23[j], y23, acc[j][b]);
                    }
                }
            }

            if (pf) {
                float* dst = s_y + (cur ^ 1) * (16 * YTILE_STR) + lb * YTILE_STR + lcc;
                *(float4*)(dst) = n0;
                *(float4*)(dst + 4) = n1;
#pragma unroll
                for (int j = 0; j < 4; j++) wcur[j] = wnext[j];
            }
            __syncthreads();
            cur ^= 1;
        }

        if (docompute) {
            float outv[4];
#pragma unroll
            for (int j = 0; j < 4; j++) {
                outv[j] = 0.0f;
#pragma unroll
                for (int b = 0; b < 16; b++) {
                    float lo, hi;
                    upk2(acc[j][b], lo, hi);
                    float s = lo + hi;
#pragma unroll
                    for (int off = 16; off > 0; off >>= 1)
                        s += __shfl_xor_sync(0xffffffffu, s, off);
                    if (lane == b) outv[j] = s;
                }
            }

            if (lane < 16) {
                int b = lane;
                float rb = s_red[b];   // scalar rsqrt factor for this batch
#pragma unroll
                for (int j = 0; j < 4; j++) {
                    if (!rv[j]) continue;
                    float val = outv[j] * rb;
                    if (typ[j] == 0) {
                        if (t < SEQLEN) {
                            float base = g_xbcconv[(b * SEQLEN + t) * CONVDIM + idx[j]];
                            st_rlx_f(&g_act[b * ACTDIM + idx[j]], silu_f(base + val));
                        }
                    } else if (typ[j] == 1) {
                        if (t < SEQLEN) {
                            float base = g_zxbcdt[(b * SEQLEN + t) * DINPROJ + (DSSM + CONVDIM) + idx[j]];
                            st_rlx_f(&g_act[b * ACTDIM + CONVDIM + idx[j]], silu_f(base + val));
                        }
                    } else {
                        if (t >= 1) out[(b * SEQLEN + (t - 1)) * DMODEL + idx[j]] = val;
                    }
                }
            }
        }

        if (t == SEQLEN) break;

        grid_barrier(cta, epoch++);   // act(t) visible

        // =================== phase B ===================
        for (int i = tid * 4; i < 1024; i += NTHR * 4) {
            int bl = i >> 8, k = i & 255;
            float4 v = ld_rlx_f4(&g_act[(bg * 4 + bl) * ACTDIM + DSSM + k]);
            *(float4*)(s_bc + i) = v;
        }
        __syncthreads();

        {
            float x   = ld_rlx_f(&g_act[bglb * ACTDIM + h * HEADDIM + dd]);
            float dtr = ld_rlx_f(&g_act[bglb * ACTDIM + CONVDIM + h]);
            float dt  = softplus_f(dtr + dtb);
            float dA  = expf(dt * Ah);
            float coef = dt * x;

            const float* bvp = s_bc + b_loc * 256;
            const float* cvp = bvp + 128;
            float accv = 0.0f;
            int p = tid;
#pragma unroll 4
            for (int n = 0; n < DSTATE; n++) {
                float s = s_state[n * 256 + p];
                s = fmaf(s, dA, coef * bvp[n]);
                accv = fmaf(s, cvp[n], accv);
                s_state[n * 256 + p] = s;
            }
            float y = fmaf(Dh, x, accv);
            float z = g_zxbcdt[(bglb * SEQLEN + t) * DINPROJ + h * HEADDIM + dd];
            float g = y * silu_f(z);

            // write un-normalized g * norm_w; r deferred to phase A
            st_rlx_f(&g_yn[bglb * DSSM + h * HEADDIM + dd], g * nw);

            // per-(batch, head) partial sum of g^2
            float gsq = g * g;
#pragma unroll
            for (int off = 16; off > 0; off >>= 1)
                gsq += __shfl_xor_sync(0xffffffffu, gsq, off);
            if (lane == 0) s_red[16 + warp] = gsq;
        }
        __syncthreads();

        if (tid < 4) {
            float part = s_red[16 + 2 * tid] + s_red[16 + 2 * tid + 1];
            st_rlx_f(&g_mspart[(bg * 4 + tid) * 32 + h], part);
        }

        grid_barrier(cta, epoch++);   // yn(t) + partials visible
    }
}

// ---------------- launcher ----------------
extern "C" void kernel_launch(void* const* d_in, const int* in_sizes, int n_in,
                              void* d_out, int out_size) {
    const float* u       = (const float*)d_in[0];
    const float* W_in    = (const float*)d_in[1];
    const float* conv_w  = (const float*)d_in[2];
    const float* conv_b  = (const float*)d_in[3];
    const float* W_rxbc  = (const float*)d_in[4];
    const float* W_rdt   = (const float*)d_in[5];
    const float* dt_bias = (const float*)d_in[6];
    const float* A_log   = (const float*)d_in[7];
    const float* D_param = (const float*)d_in[8];
    const float* norm_w  = (const float*)d_in[9];
    const float* W_out   = (const float*)d_in[10];
    float* out = (float*)d_out;

    static int smem_set = 0;
    const int SMEM_BYTES = SM_TOTALF * 4;
    if (!smem_set) {
        cudaFuncSetAttribute(scan_kernel, cudaFuncAttributeMaxDynamicSharedMemorySize, SMEM_BYTES);
        smem_set = 1;
    }

    dim3 gIn((DINPROJ + 63) / 64, (BATCH * SEQLEN) / 64);
    inproj_kernel<<<gIn, 256>>>(u, W_in);

    int convN = BATCH * SEQLEN * CONVDIM;
    conv_kernel<<<(convN + 255) / 256, 256>>>(conv_w, conv_b);

    scan_kernel<<<NCTA, NTHR, SMEM_BYTES>>>(W_rxbc, W_rdt, dt_bias, A_log,
                                            D_param, norm_w, W_out, out);
}

// round 8
// speedup vs baseline: 1.5740x; 1.1386x over previous
#include <cuda_runtime.h>
#include <math.h>

// ---------------- problem constants ----------------
#define BATCH     16
#define SEQLEN    512
#define DMODEL    1024
#define DSTATE    128
#define DCONV     4
#define HEADDIM   64
#define DSSM      2048
#define NHEADS    32
#define CONVDIM   2304            // DSSM + 2*DSTATE
#define DINPROJ   4384            // 2*DSSM + 2*DSTATE + NHEADS
#define ACTDIM    2336            // CONVDIM + NHEADS
#define NCTA      128
#define NTHR      256
#define EPSV      1e-5f

// scan SMEM layout (floats)
#define SM_STATE  0                        // 256*132 = 33792 (state[p][n], pad 132)
#define SM_Y      33792                    // 2*2112 = 4224 (y tiles; reused as reduce scratch)
#define SM_BC     (33792 + 4224)           // 1024
#define SM_RED    (33792 + 4224 + 1024)    // 32
#define SM_TOTALF (33792 + 4224 + 1024 + 32)
#define YTILE_STR 132

// ---------------- device scratch ----------------
__device__ float g_zxbcdt[BATCH * SEQLEN * DINPROJ];
__device__ float g_xbcconv[BATCH * SEQLEN * CONVDIM];
__device__ float g_act[BATCH * ACTDIM];
__device__ float g_yn[BATCH * DSSM];            // UN-normalized g*norm_w (r deferred)
__device__ float g_mspart[BATCH * 32];          // per (batch, head) sum of g^2
__device__ unsigned g_arrive[NCTA * 32];        // padded per-CTA epoch flags (monotonic)
__device__ unsigned g_release;                  // master release word (monotonic)

// ---------------- helpers ----------------
__device__ __forceinline__ float silu_f(float v) { return v / (1.0f + expf(-v)); }
__device__ __forceinline__ float softplus_f(float v) { return (v > 20.0f) ? v : log1pf(expf(v)); }

__device__ __forceinline__ void upk2(unsigned long long v, float& lo, float& hi) {
    unsigned a, b;
    asm("mov.b64 {%0, %1}, %2;" : "=r"(a), "=r"(b) : "l"(v));
    lo = __uint_as_float(a); hi = __uint_as_float(b);
}
__device__ __forceinline__ unsigned long long pk2(float lo, float hi) {
    unsigned long long r;
    asm("mov.b64 %0, {%1, %2};" : "=l"(r) : "r"(__float_as_uint(lo)), "r"(__float_as_uint(hi)));
    return r;
}
__device__ __forceinline__ unsigned long long fma2(unsigned long long a, unsigned long long b,
                                                   unsigned long long c) {
    unsigned long long d;
    asm("fma.rn.f32x2 %0, %1, %2, %3;" : "=l"(d) : "l"(a), "l"(b), "l"(c));
    return d;
}
__device__ __forceinline__ unsigned long long mul2(unsigned long long a, unsigned long long b) {
    unsigned long long d;
    asm("mul.rn.f32x2 %0, %1, %2;" : "=l"(d) : "l"(a), "l"(b));
    return d;
}
__device__ __forceinline__ unsigned tf32_of(float x) {
    unsigned r;
    asm("cvt.rna.tf32.f32 %0, %1;" : "=r"(r) : "f"(x));
    return r;
}

// ---- strong (L2-coherent) memory ops ----
__device__ __forceinline__ void st_release_u(unsigned* p, unsigned v) {
    asm volatile("st.release.gpu.global.u32 [%0], %1;" :: "l"(p), "r"(v) : "memory");
}
__device__ __forceinline__ unsigned ld_acquire_u(const unsigned* p) {
    unsigned v;
    asm volatile("ld.acquire.gpu.global.u32 %0, [%1];" : "=r"(v) : "l"(p) : "memory");
    return v;
}
__device__ __forceinline__ float ld_rlx_f(const float* p) {
    float v;
    asm volatile("ld.relaxed.gpu.global.f32 %0, [%1];" : "=f"(v) : "l"(p) : "memory");
    return v;
}
__device__ __forceinline__ void st_rlx_f(float* p, float v) {
    asm volatile("st.relaxed.gpu.global.f32 [%0], %1;" :: "l"(p), "f"(v) : "memory");
}
__device__ __forceinline__ float4 ld_rlx_f4(const float* p) {
    float4 v;
    asm volatile("ld.relaxed.gpu.global.v4.f32 {%0,%1,%2,%3}, [%4];"
                 : "=f"(v.x), "=f"(v.y), "=f"(v.z), "=f"(v.w) : "l"(p) : "memory");
    return v;
}

union F4U { float4 f; unsigned long long u[2]; };

// flag-based grid barrier (proven in R7)
__device__ __forceinline__ void grid_barrier(int cta, unsigned epoch) {
    __syncthreads();
    if (threadIdx.x == 0) st_release_u(&g_arrive[cta * 32], epoch);
    if (cta == 0) {
        if (threadIdx.x < 128) {
            while (ld_acquire_u(&g_arrive[threadIdx.x * 32]) < epoch) { }
        }
        __syncthreads();
        if (threadIdx.x == 0) st_release_u(&g_release, epoch);
    } else {
        if (threadIdx.x == 0) {
            while (ld_acquire_u(&g_release) < epoch) { }
        }
    }
    __syncthreads();
}

// ---------------- kernel 1: in_proj GEMM, tf32 mma with split compensation --------
// C[8192,4384] = U[8192,1024] @ Win[4384,1024]^T
// Tile 128(M) x 64(N), K-chunk 32, 8 warps (4 m-subtiles x 2 n-subtiles of 32x32).
#define ASTR 36
#define IP_AH 0                      // A hi: 2 bufs x 128*36
#define IP_AL (2 * 128 * ASTR)       // A lo
#define IP_BH (4 * 128 * ASTR)       // B hi: 2 bufs x 64*36
#define IP_BL (4 * 128 * ASTR + 2 * 64 * ASTR)
#define IP_TOTALF (4 * 128 * ASTR + 4 * 64 * ASTR)

__device__ __forceinline__ void mma_tf32(float* d, const unsigned* a, const unsigned* b) {
    asm volatile(
        "mma.sync.aligned.m16n8k8.row.col.f32.tf32.tf32.f32 "
        "{%0,%1,%2,%3}, {%4,%5,%6,%7}, {%8,%9}, {%0,%1,%2,%3};"
        : "+f"(d[0]), "+f"(d[1]), "+f"(d[2]), "+f"(d[3])
        : "r"(a[0]), "r"(a[1]), "r"(a[2]), "r"(a[3]), "r"(b[0]), "r"(b[1]));
}

__global__ __launch_bounds__(256) void inproj_kernel(const float* __restrict__ U,
                                                     const float* __restrict__ Win) {
    extern __shared__ float smf[];
    const int N = DINPROJ;
    const int K = DMODEL;

    const int tid  = threadIdx.x;
    const int lane = tid & 31;
    const int warp = tid >> 5;
    const int mbase = blockIdx.y * 128;
    const int nbase = blockIdx.x * 64;
    const int mrow0 = (warp & 3) * 32;
    const int ncol0 = (warp >> 2) * 32;

    // global load mapping
    const int arow = tid >> 1;               // 0..127
    const int acb  = (tid & 1) * 16;         // 0 or 16
    const int brow = tid >> 2;               // 0..63
    const int bcb  = (tid & 3) * 8;          // 0,8,16,24

    float C[2][4][4];
#pragma unroll
    for (int mt = 0; mt < 2; mt++)
#pragma unroll
        for (int nt = 0; nt < 4; nt++)
#pragma unroll
            for (int e = 0; e < 4; e++) C[mt][nt][e] = 0.0f;

    float4 aReg[4];
    float4 bReg[2];

    auto ldg_chunk = [&](int k0) {
#pragma unroll
        for (int q = 0; q < 4; q++)
            aReg[q] = *(const float4*)(U + (mbase + arow) * K + k0 + acb + q * 4);
        if (nbase + brow < N) {
#pragma unroll
            for (int q = 0; q < 2; q++)
                bReg[q] = *(const float4*)(Win + (nbase + brow) * K + k0 + bcb + q * 4);
        } else {
            bReg[0] = make_float4(0.f, 0.f, 0.f, 0.f);
            bReg[1] = make_float4(0.f, 0.f, 0.f, 0.f);
        }
    };

    auto sts_chunk = [&](int buf) {
        float* Ah = smf + IP_AH + buf * 128 * ASTR;
        float* Al = smf + IP_AL + buf * 128 * ASTR;
        float* Bh = smf + IP_BH + buf * 64 * ASTR;
        float* Bl = smf + IP_BL + buf * 64 * ASTR;
#pragma unroll
        for (int q = 0; q < 4; q++) {
            const float* v = (const float*)&aReg[q];
#pragma unroll
            for (int e = 0; e < 4; e++) {
                float x = v[e];
                unsigned hb = tf32_of(x);
                float hf = __uint_as_float(hb);
                unsigned lb = tf32_of(x - hf);
                Ah[arow * ASTR + acb + q * 4 + e] = hf;
                Al[arow * ASTR + acb + q * 4 + e] = __uint_as_float(lb);
            }
        }
#pragma unroll
        for (int q = 0; q < 2; q++) {
            const float* v = (const float*)&bReg[q];
#pragma unroll
            for (int e = 0; e < 4; e++) {
                float x = v[e];
                unsigned hb = tf32_of(x);
                float hf = __uint_as_float(hb);
                unsigned lb = tf32_of(x - hf);
                Bh[brow * ASTR + bcb + q * 4 + e] = hf;
                Bl[brow * ASTR + bcb + q * 4 + e] = __uint_as_float(lb);
            }
        }
    };

    ldg_chunk(0);
    sts_chunk(0);
    __syncthreads();

    const int NCHUNK = K / 32;    // 32
    for (int c = 0; c < NCHUNK; c++) {
        int buf = c & 1;
        if (c + 1 < NCHUNK) ldg_chunk((c + 1) * 32);

        const unsigned* Ah = (const unsigned*)(smf + IP_AH + buf * 128 * ASTR);
        const unsigned* Al = (const unsigned*)(smf + IP_AL + buf * 128 * ASTR);
        const unsigned* Bh = (const unsigned*)(smf + IP_BH + buf * 64 * ASTR);
        const unsigned* Bl = (const unsigned*)(smf + IP_BL + buf * 64 * ASTR);

#pragma unroll
        for (int ks = 0; ks < 4; ks++) {
            int kc = ks * 8;
            unsigned ah[2][4], al[2][4], bh[4][2], bl[4][2];
#pragma unroll
            for (int mt = 0; mt < 2; mt++) {
                int r0 = mrow0 + mt * 16 + (lane >> 2);
                int cc = kc + (lane & 3);
                ah[mt][0] = Ah[r0 * ASTR + cc];
                ah[mt][1] = Ah[(r0 + 8) * ASTR + cc];
                ah[mt][2] = Ah[r0 * ASTR + cc + 4];
                ah[mt][3] = Ah[(r0 + 8) * ASTR + cc + 4];
                al[mt][0] = Al[r0 * ASTR + cc];
                al[mt][1] = Al[(r0 + 8) * ASTR + cc];
                al[mt][2] = Al[r0 * ASTR + cc + 4];
                al[mt][3] = Al[(r0 + 8) * ASTR + cc + 4];
            }
#pragma unroll
            for (int nt = 0; nt < 4; nt++) {
                int n0 = ncol0 + nt * 8 + (lane >> 2);
                int kk = kc + (lane & 3);
                bh[nt][0] = Bh[n0 * ASTR + kk];
                bh[nt][1] = Bh[n0 * ASTR + kk + 4];
                bl[nt][0] = Bl[n0 * ASTR + kk];
                bl[nt][1] = Bl[n0 * ASTR + kk + 4];
            }
#pragma unroll
            for (int mt = 0; mt < 2; mt++)
#pragma unroll
                for (int nt = 0; nt < 4; nt++) {
                    mma_tf32(C[mt][nt], ah[mt], bh[nt]);
                    mma_tf32(C[mt][nt], al[mt], bh[nt]);
                    mma_tf32(C[mt][nt], ah[mt], bl[nt]);
                }
        }

        __syncthreads();
        if (c + 1 < NCHUNK) {
            sts_chunk(buf ^ 1);
            __syncthreads();
        }
    }

    // epilogue: C frag m16n8 layout
#pragma unroll
    for (int mt = 0; mt < 2; mt++) {
        int row = mbase + mrow0 + mt * 16 + (lane >> 2);
#pragma unroll
        for (int nt = 0; nt < 4; nt++) {
            int col = nbase + ncol0 + nt * 8 + (lane & 3) * 2;
            if (col < N) {
                g_zxbcdt[row * N + col]           = C[mt][nt][0];
                g_zxbcdt[row * N + col + 1]       = C[mt][nt][1];
                g_zxbcdt[(row + 8) * N + col]     = C[mt][nt][2];
                g_zxbcdt[(row + 8) * N + col + 1] = C[mt][nt][3];
            }
        }
    }
}

// ---------------- kernel 2: causal depthwise conv ----------------
__global__ __launch_bounds__(256) void conv_kernel(const float* __restrict__ conv_w,
                                                   const float* __restrict__ conv_b) {
    int idx = blockIdx.x * blockDim.x + threadIdx.x;
    if (idx >= BATCH * SEQLEN * CONVDIM) return;
    int c  = idx % CONVDIM;
    int bt = idx / CONVDIM;
    int t  = bt % SEQLEN;
    int b  = bt / SEQLEN;
    float accv = conv_b[c];
#pragma unroll
    for (int k = 0; k < DCONV; k++) {
        int tt = t + k - (DCONV - 1);
        if (tt >= 0)
            accv = fmaf(g_zxbcdt[(b * SEQLEN + tt) * DINPROJ + DSSM + c],
                        conv_w[c * DCONV + k], accv);
    }
    g_xbcconv[idx] = accv;
}

// ---------------- kernel 3: persistent scan ----------------
__global__ __launch_bounds__(NTHR, 1) void scan_kernel(
    const float* __restrict__ W_rxbc, const float* __restrict__ W_rdt,
    const float* __restrict__ dt_bias, const float* __restrict__ A_log,
    const float* __restrict__ D_param, const float* __restrict__ norm_w,
    const float* __restrict__ W_out, float* __restrict__ out) {

    extern __shared__ float sm[];
    float* s_state = sm + SM_STATE;       // state[p][n], stride 132
    float* s_y     = sm + SM_Y;           // 2 y tiles; later reduce scratch
    float* s_bc    = sm + SM_BC;
    float* s_red   = sm + SM_RED;
    __shared__ unsigned s_base;

    const int tid  = threadIdx.x;
    const int cta  = blockIdx.x;
    const int lane = tid & 31;
    const int warp = tid >> 5;

    if (tid == 0) s_base = ld_acquire_u(&g_release);
    for (int i = cta * NTHR + tid; i < BATCH * DSSM; i += NCTA * NTHR) st_rlx_f(&g_yn[i], 0.0f);
    for (int i = tid; i < 256 * 132; i += NTHR) s_state[i] = 0.0f;
    __syncthreads();
    unsigned epoch = s_base + 1;

    // ---- phase A task setup: 4 rows per warp ----
    const int hasdt = (cta < NHEADS) ? 1 : 0;
    const int ntask = 18 + hasdt + 8;
    bool rv[4];
    const float* wr[4];
    bool any2 = false;
#pragma unroll
    for (int j = 0; j < 4; j++) {
        int r = warp * 4 + j;
        rv[j] = (r < ntask);
        wr[j] = W_rxbc;
        if (rv[j]) {
            if (r < 18) { wr[j] = W_rxbc + (cta * 18 + r) * DSSM; }
            else {
                int rr = r - 18;
                if (hasdt && rr == 0) { wr[j] = W_rdt + cta * DSSM; }
                else { rr -= hasdt; wr[j] = W_out + (cta * 8 + rr) * DSSM; any2 = true; }
            }
        }
    }
    const bool anyrow = rv[0];

    const int lb = tid >> 4;            // batch 0..15 (y tile loader)
    const int lcc = (tid & 15) * 8;     // col 0..120

    // ---- phase B constants ----
    const int h  = cta & 31;
    const int bg = cta >> 5;
    const int b_loc = tid >> 6;
    const int dd    = tid & 63;
    const int bglb  = bg * 4 + b_loc;
    const float Ah  = -expf(A_log[h]);
    const float dtb = dt_bias[h];
    const float Dh  = D_param[h];
    const float nw  = norm_w[h * HEADDIM + dd];

    grid_barrier(cta, epoch++);

    for (int t = 0; t <= SEQLEN; t++) {
        // =================== phase A ===================
        const bool docompute = anyrow && (t < SEQLEN || any2);

        if (tid < 16) {
            const float* mp = g_mspart + tid * 32;
            float tot = 0.0f;
#pragma unroll
            for (int q = 0; q < 8; q++) {
                float4 v = ld_rlx_f4(mp + q * 4);
                tot += v.x + v.y + v.z + v.w;
            }
            s_red[tid] = rsqrtf(tot * (1.0f / (float)DSSM) + EPSV);
        }

        unsigned long long acc[4][16];
#pragma unroll
        for (int j = 0; j < 4; j++)
#pragma unroll
            for (int b = 0; b < 16; b++) acc[j][b] = 0ULL;

        {
            const float* src = g_yn + lb * DSSM + lcc;
            float4 v0 = ld_rlx_f4(src);
            float4 v1 = ld_rlx_f4(src + 4);
            float* dst = s_y + lb * YTILE_STR + lcc;
            *(float4*)(dst) = v0;
            *(float4*)(dst + 4) = v1;
        }
        F4U wcur[4];
#pragma unroll
        for (int j = 0; j < 4; j++)
            wcur[j].f = *(const float4*)(wr[j] + lane * 4);
        __syncthreads();

        int cur = 0;
        for (int blk = 0; blk < 16; blk++) {
            float4 n0, n1;
            const bool pf = (blk < 15);
            if (pf) {
                const float* src = g_yn + lb * DSSM + (blk + 1) * 128 + lcc;
                n0 = ld_rlx_f4(src);
                n1 = ld_rlx_f4(src + 4);
            }
            F4U wnext[4];
            if (pf) {
#pragma unroll
                for (int j = 0; j < 4; j++)
                    wnext[j].f = *(const float4*)(wr[j] + (blk + 1) * 128 + lane * 4);
            }

            if (docompute) {
                unsigned long long w01[4], w23[4];
#pragma unroll
                for (int j = 0; j < 4; j++) { w01[j] = wcur[j].u[0]; w23[j] = wcur[j].u[1]; }
                const float* yt = s_y + cur * (16 * YTILE_STR) + lane * 4;
#pragma unroll
                for (int b = 0; b < 16; b++) {
                    F4U yv;
                    yv.f = *(const float4*)(yt + b * YTILE_STR);
                    unsigned long long y01 = yv.u[0];
                    unsigned long long y23 = yv.u[1];
#pragma unroll
                    for (int j = 0; j < 4; j++) {
                        acc[j][b] = fma2(w01[j], y01, acc[j][b]);
                        acc[j][b] = fma2(w23[j], y23, acc[j][b]);
                    }
                }
            }

            if (pf) {
                float* dst = s_y + (cur ^ 1) * (16 * YTILE_STR) + lb * YTILE_STR + lcc;
                *(float4*)(dst) = n0;
                *(float4*)(dst + 4) = n1;
#pragma unroll
                for (int j = 0; j < 4; j++) wcur[j] = wnext[j];
            }
            __syncthreads();
            cur ^= 1;
        }

        // ---- reduction: 2-level shfl + smem transpose (s_y reused as scratch) ----
#pragma unroll
        for (int j = 0; j < 4; j++) {
#pragma unroll
            for (int b = 0; b < 16; b++) {
                float lo, hi;
                upk2(acc[j][b], lo, hi);
                float s = lo + hi;
                s += __shfl_xor_sync(0xffffffffu, s, 16);
                s += __shfl_xor_sync(0xffffffffu, s, 8);
                if (lane < 8) s_y[warp * 512 + (j * 16 + b) * 8 + lane] = s;
            }
        }
        __syncthreads();

        // 512 groups (warp, j, b); each thread finishes 2
#pragma unroll
        for (int gi = 0; gi < 2; gi++) {
            int g = tid + gi * 256;
            int w = g >> 6;
            int jb = g & 63;
            int j = jb >> 4;
            int b = jb & 15;
            int r = w * 4 + j;
            if (r >= ntask) continue;
            const float* sp = s_y + g * 8;
            float4 v0 = *(const float4*)sp;
            float4 v1 = *(const float4*)(sp + 4);
            float sum = ((v0.x + v0.y) + (v0.z + v0.w)) + ((v1.x + v1.y) + (v1.z + v1.w));
            float val = sum * s_red[b];
            if (r < 18) {
                if (t < SEQLEN) {
                    int idxv = cta * 18 + r;
                    float base = g_xbcconv[(b * SEQLEN + t) * CONVDIM + idxv];
                    st_rlx_f(&g_act[b * ACTDIM + idxv], silu_f(base + val));
                }
            } else if (hasdt && r == 18) {
                if (t < SEQLEN) {
                    float base = g_zxbcdt[(b * SEQLEN + t) * DINPROJ + (DSSM + CONVDIM) + cta];
                    st_rlx_f(&g_act[b * ACTDIM + CONVDIM + cta], silu_f(base + val));
                }
            } else {
                int idxv = cta * 8 + (r - 18 - hasdt);
                if (t >= 1) out[(b * SEQLEN + (t - 1)) * DMODEL + idxv] = val;
            }
        }

        if (t == SEQLEN) break;

        grid_barrier(cta, epoch++);   // act(t) visible

        // =================== phase B ===================
        for (int i = tid * 4; i < 1024; i += NTHR * 4) {
            int bl = i >> 8, k = i & 255;
            float4 v = ld_rlx_f4(&g_act[(bg * 4 + bl) * ACTDIM + DSSM + k]);
            *(float4*)(s_bc + i) = v;
        }
        __syncthreads();

        {
            float x   = ld_rlx_f(&g_act[bglb * ACTDIM + h * HEADDIM + dd]);
            float dtr = ld_rlx_f(&g_act[bglb * ACTDIM + CONVDIM + h]);
            float dt  = softplus_f(dtr + dtb);
            float dA  = expf(dt * Ah);
            float coef = dt * x;

            unsigned long long dA2 = pk2(dA, dA);
            unsigned long long cf2 = pk2(coef, coef);
            unsigned long long acc2 = 0ULL;

            const float* bvp = s_bc + b_loc * 256;
            float* sp = s_state + tid * 132;
#pragma unroll 4
            for (int n = 0; n < DSTATE; n += 4) {
                F4U sv, bv, cv;
                sv.f = *(float4*)(sp + n);
                bv.f = *(const float4*)(bvp + n);
                cv.f = *(const float4*)(bvp + 128 + n);
                sv.u[0] = fma2(sv.u[0], dA2, mul2(cf2, bv.u[0]));
                sv.u[1] = fma2(sv.u[1], dA2, mul2(cf2, bv.u[1]));
                acc2 = fma2(sv.u[0], cv.u[0], acc2);
                acc2 = fma2(sv.u[1], cv.u[1], acc2);
                *(float4*)(sp + n) = sv.f;
            }
            float alo, ahi;
            upk2(acc2, alo, ahi);
            float y = fmaf(Dh, x, alo + ahi);
            float z = g_zxbcdt[(bglb * SEQLEN + t) * DINPROJ + h * HEADDIM + dd];
            float g = y * silu_f(z);

            st_rlx_f(&g_yn[bglb * DSSM + h * HEADDIM + dd], g * nw);

            float gsq = g * g;
#pragma unroll
            for (int off = 16; off > 0; off >>= 1)
                gsq += __shfl_xor_sync(0xffffffffu, gsq, off);
            if (lane == 0) s_red[16 + warp] = gsq;
        }
        __syncthreads();

        if (tid < 4) {
            float part = s_red[16 + 2 * tid] + s_red[16 + 2 * tid + 1];
            st_rlx_f(&g_mspart[(bg * 4 + tid) * 32 + h], part);
        }

        grid_barrier(cta, epoch++);   // yn(t) + partials visible
    }
}

// ---------------- launcher ----------------
extern "C" void kernel_launch(void* const* d_in, const int* in_sizes, int n_in,
                              void* d_out, int out_size) {
    const float* u       = (const float*)d_in[0];
    const float* W_in    = (const float*)d_in[1];
    const float* conv_w  = (const float*)d_in[2];
    const float* conv_b  = (const float*)d_in[3];
    const float* W_rxbc  = (const float*)d_in[4];
    const float* W_rdt   = (const float*)d_in[5];
    const float* dt_bias = (const float*)d_in[6];
    const float* A_log   = (const float*)d_in[7];
    const float* D_param = (const float*)d_in[8];
    const float* norm_w  = (const float*)d_in[9];
    const float* W_out   = (const float*)d_in[10];
    float* out = (float*)d_out;

    static int attr_set = 0;
    const int SCAN_SMEM = SM_TOTALF * 4;
    const int IP_SMEM   = IP_TOTALF * 4;
    if (!attr_set) {
        cudaFuncSetAttribute(scan_kernel, cudaFuncAttributeMaxDynamicSharedMemorySize, SCAN_SMEM);
        cudaFuncSetAttribute(inproj_kernel, cudaFuncAttributeMaxDynamicSharedMemorySize, IP_SMEM);
        attr_set = 1;
    }

    dim3 gIn((DINPROJ + 63) / 64, (BATCH * SEQLEN) / 128);
    inproj_kernel<<<gIn, 256, IP_SMEM>>>(u, W_in);

    int convN = BATCH * SEQLEN * CONVDIM;
    conv_kernel<<<(convN + 255) / 256, 256>>>(conv_w, conv_b);

    scan_kernel<<<NCTA, NTHR, SCAN_SMEM>>>(W_rxbc, W_rdt, dt_bias, A_log,
                                           D_param, norm_w, W_out, out);
}

// round 9
// speedup vs baseline: 2.1876x; 1.3898x over previous
#include <cuda_runtime.h>
#include <cuda_bf16.h>
#include <math.h>

// ---------------- problem constants ----------------
#define BATCH     16
#define SEQLEN    512
#define DMODEL    1024
#define DSTATE    128
#define DCONV     4
#define HEADDIM   64
#define DSSM      2048
#define NHEADS    32
#define CONVDIM   2304            // DSSM + 2*DSTATE
#define DINPROJ   4384            // 2*DSSM + 2*DSTATE + NHEADS
#define ACTDIM    2336            // CONVDIM + NHEADS
#define NCTA      128
#define NTHR      256
#define EPSV      1e-5f

// scan SMEM layout (floats)
#define SM_STATE  0                        // 256*132 = 33792 (state[p][n], pad 132)
#define SM_Y      33792                    // 4096 (warp-partial reduce scratch)
#define SM_BC     (33792 + 4096)           // 1024
#define SM_RED    (33792 + 4096 + 1024)    // 32
#define SM_TOTALF (33792 + 4096 + 1024 + 32)

// ---------------- device scratch ----------------
__device__ float g_zxbcdt[BATCH * SEQLEN * DINPROJ];
__device__ float g_xbcconv[BATCH * SEQLEN * CONVDIM];
__device__ float g_act[BATCH * ACTDIM];
__device__ float g_mspart[BATCH * 32];          // per (batch, head) sum of g^2
__device__ unsigned g_arrive[NCTA * 32];        // padded per-CTA epoch flags (monotonic)
__device__ unsigned g_release;                  // master release word (monotonic)
// W fragments: [cta][s(128)][hilo(2)][lane(32)][nt(4)][b0,b1] as u32 -> 32 MB
__device__ unsigned g_wfrag[128 * 128 * 2 * 256];
// Y fragments: [hilo][s(128)][lane(32)][reg(4)] as u32 (bf16x2) -> 128 KB
__device__ unsigned g_yfrag[2 * 128 * 32 * 4];

// ---------------- helpers ----------------
__device__ __forceinline__ float silu_f(float v) { return v / (1.0f + expf(-v)); }
__device__ __forceinline__ float softplus_f(float v) { return (v > 20.0f) ? v : log1pf(expf(v)); }

__device__ __forceinline__ void upk2(unsigned long long v, float& lo, float& hi) {
    unsigned a, b;
    asm("mov.b64 {%0, %1}, %2;" : "=r"(a), "=r"(b) : "l"(v));
    lo = __uint_as_float(a); hi = __uint_as_float(b);
}
__device__ __forceinline__ unsigned long long pk2(float lo, float hi) {
    unsigned long long r;
    asm("mov.b64 %0, {%1, %2};" : "=l"(r) : "r"(__float_as_uint(lo)), "r"(__float_as_uint(hi)));
    return r;
}
__device__ __forceinline__ unsigned long long fma2(unsigned long long a, unsigned long long b,
                                                   unsigned long long c) {
    unsigned long long d;
    asm("fma.rn.f32x2 %0, %1, %2, %3;" : "=l"(d) : "l"(a), "l"(b), "l"(c));
    return d;
}
__device__ __forceinline__ unsigned long long mul2(unsigned long long a, unsigned long long b) {
    unsigned long long d;
    asm("mul.rn.f32x2 %0, %1, %2;" : "=l"(d) : "l"(a), "l"(b));
    return d;
}
__device__ __forceinline__ unsigned tf32_of(float x) {
    unsigned r;
    asm("cvt.rna.tf32.f32 %0, %1;" : "=r"(r) : "f"(x));
    return r;
}

// ---- strong (L2-coherent) memory ops ----
__device__ __forceinline__ void st_release_u(unsigned* p, unsigned v) {
    asm volatile("st.release.gpu.global.u32 [%0], %1;" :: "l"(p), "r"(v) : "memory");
}
__device__ __forceinline__ unsigned ld_acquire_u(const unsigned* p) {
    unsigned v;
    asm volatile("ld.acquire.gpu.global.u32 %0, [%1];" : "=r"(v) : "l"(p) : "memory");
    return v;
}
__device__ __forceinline__ float ld_rlx_f(const float* p) {
    float v;
    asm volatile("ld.relaxed.gpu.global.f32 %0, [%1];" : "=f"(v) : "l"(p) : "memory");
    return v;
}
__device__ __forceinline__ void st_rlx_f(float* p, float v) {
    asm volatile("st.relaxed.gpu.global.f32 [%0], %1;" :: "l"(p), "f"(v) : "memory");
}
__device__ __forceinline__ void st_rlx_u(unsigned* p, unsigned v) {
    asm volatile("st.relaxed.gpu.global.u32 [%0], %1;" :: "l"(p), "r"(v) : "memory");
}
__device__ __forceinline__ void st_rlx_b16(unsigned short* p, unsigned short v) {
    asm volatile("st.relaxed.gpu.global.b16 [%0], %1;" :: "l"(p), "h"(v) : "memory");
}
__device__ __forceinline__ float4 ld_rlx_f4(const float* p) {
    float4 v;
    asm volatile("ld.relaxed.gpu.global.v4.f32 {%0,%1,%2,%3}, [%4];"
                 : "=f"(v.x), "=f"(v.y), "=f"(v.z), "=f"(v.w) : "l"(p) : "memory");
    return v;
}

union F4U { float4 f; unsigned long long u[2]; unsigned v[4]; };

// flag-based grid barrier (proven R7/R8)
__device__ __forceinline__ void grid_barrier(int cta, unsigned epoch) {
    __syncthreads();
    if (threadIdx.x == 0) st_release_u(&g_arrive[cta * 32], epoch);
    if (cta == 0) {
        if (threadIdx.x < 128) {
            while (ld_acquire_u(&g_arrive[threadIdx.x * 32]) < epoch) { }
        }
        __syncthreads();
        if (threadIdx.x == 0) st_release_u(&g_release, epoch);
    } else {
        if (threadIdx.x == 0) {
            while (ld_acquire_u(&g_release) < epoch) { }
        }
    }
    __syncthreads();
}

// bf16 MMA: D[16x8] += A[16x16] * B[16x8]
__device__ __forceinline__ void mma_bf16(float* d, const unsigned* a, unsigned b0, unsigned b1) {
    asm volatile(
        "mma.sync.aligned.m16n8k16.row.col.f32.bf16.bf16.f32 "
        "{%0,%1,%2,%3}, {%4,%5,%6,%7}, {%8,%9}, {%0,%1,%2,%3};"
        : "+f"(d[0]), "+f"(d[1]), "+f"(d[2]), "+f"(d[3])
        : "r"(a[0]), "r"(a[1]), "r"(a[2]), "r"(a[3]), "r"(b0), "r"(b1));
}

// ---------------- kernel 0: precompute W fragments (bf16 hi/lo split) ----------------
__global__ __launch_bounds__(256) void wfrag_kernel(const float* __restrict__ W_rxbc,
                                                    const float* __restrict__ W_rdt,
                                                    const float* __restrict__ W_out) {
    int idx = blockIdx.x * 256 + threadIdx.x;      // < 128*128*32*4
    int nt   = idx & 3;
    int lane = (idx >> 2) & 31;
    int s    = (idx >> 7) & 127;
    int cta  = idx >> 14;
    int hasdt = (cta < NHEADS) ? 1 : 0;
    int ntask = 18 + hasdt + 8;
    int n_local = nt * 8 + (lane >> 2);
    int k0 = s * 16 + (lane & 3) * 2;

    float w00 = 0.f, w01 = 0.f, w10 = 0.f, w11 = 0.f;
    if (n_local < ntask) {
        const float* p;
        if (n_local < 18) p = W_rxbc + (size_t)(cta * 18 + n_local) * DSSM;
        else if (hasdt && n_local == 18) p = W_rdt + (size_t)cta * DSSM;
        else p = W_out + (size_t)(cta * 8 + n_local - 18 - hasdt) * DSSM;
        w00 = p[k0]; w01 = p[k0 + 1]; w10 = p[k0 + 8]; w11 = p[k0 + 9];
    }

    unsigned short h00, l00, h01, l01, h10, l10, h11, l11;
    {
        __nv_bfloat16 h;
        h = __float2bfloat16(w00); h00 = __bfloat16_as_ushort(h);
        l00 = __bfloat16_as_ushort(__float2bfloat16(w00 - __bfloat162float(h)));
        h = __float2bfloat16(w01); h01 = __bfloat16_as_ushort(h);
        l01 = __bfloat16_as_ushort(__float2bfloat16(w01 - __bfloat162float(h)));
        h = __float2bfloat16(w10); h10 = __bfloat16_as_ushort(h);
        l10 = __bfloat16_as_ushort(__float2bfloat16(w10 - __bfloat162float(h)));
        h = __float2bfloat16(w11); h11 = __bfloat16_as_ushort(h);
        l11 = __bfloat16_as_ushort(__float2bfloat16(w11 - __bfloat162float(h)));
    }

    size_t basehi = ((size_t)(cta * 128 + s) * 2) * 256 + lane * 8 + nt * 2;
    g_wfrag[basehi]       = (unsigned)h00 | ((unsigned)h01 << 16);
    g_wfrag[basehi + 1]   = (unsigned)h10 | ((unsigned)h11 << 16);
    g_wfrag[basehi + 256] = (unsigned)l00 | ((unsigned)l01 << 16);
    g_wfrag[basehi + 257] = (unsigned)l10 | ((unsigned)l11 << 16);
}

// ---------------- kernel 1: in_proj GEMM, tf32 mma (unchanged R8) --------
#define ASTR 36
#define IP_AH 0
#define IP_AL (2 * 128 * ASTR)
#define IP_BH (4 * 128 * ASTR)
#define IP_BL (4 * 128 * ASTR + 2 * 64 * ASTR)
#define IP_TOTALF (4 * 128 * ASTR + 4 * 64 * ASTR)

__device__ __forceinline__ void mma_tf32(float* d, const unsigned* a, const unsigned* b) {
    asm volatile(
        "mma.sync.aligned.m16n8k8.row.col.f32.tf32.tf32.f32 "
        "{%0,%1,%2,%3}, {%4,%5,%6,%7}, {%8,%9}, {%0,%1,%2,%3};"
        : "+f"(d[0]), "+f"(d[1]), "+f"(d[2]), "+f"(d[3])
        : "r"(a[0]), "r"(a[1]), "r"(a[2]), "r"(a[3]), "r"(b[0]), "r"(b[1]));
}

__global__ __launch_bounds__(256) void inproj_kernel(const float* __restrict__ U,
                                                     const float* __restrict__ Win) {
    extern __shared__ float smf[];
    const int N = DINPROJ;
    const int K = DMODEL;

    const int tid  = threadIdx.x;
    const int lane = tid & 31;
    const int warp = tid >> 5;
    const int mbase = blockIdx.y * 128;
    const int nbase = blockIdx.x * 64;
    const int mrow0 = (warp & 3) * 32;
    const int ncol0 = (warp >> 2) * 32;

    const int arow = tid >> 1;
    const int acb  = (tid & 1) * 16;
    const int brow = tid >> 2;
    const int bcb  = (tid & 3) * 8;

    float C[2][4][4];
#pragma unroll
    for (int mt = 0; mt < 2; mt++)
#pragma unroll
        for (int nt = 0; nt < 4; nt++)
#pragma unroll
            for (int e = 0; e < 4; e++) C[mt][nt][e] = 0.0f;

    float4 aReg[4];
    float4 bReg[2];

    auto ldg_chunk = [&](int k0) {
#pragma unroll
        for (int q = 0; q < 4; q++)
            aReg[q] = *(const float4*)(U + (mbase + arow) * K + k0 + acb + q * 4);
        if (nbase + brow < N) {
#pragma unroll
            for (int q = 0; q < 2; q++)
                bReg[q] = *(const float4*)(Win + (nbase + brow) * K + k0 + bcb + q * 4);
        } else {
            bReg[0] = make_float4(0.f, 0.f, 0.f, 0.f);
            bReg[1] = make_float4(0.f, 0.f, 0.f, 0.f);
        }
    };

    auto sts_chunk = [&](int buf) {
        float* Ah = smf + IP_AH + buf * 128 * ASTR;
        float* Al = smf + IP_AL + buf * 128 * ASTR;
        float* Bh = smf + IP_BH + buf * 64 * ASTR;
        float* Bl = smf + IP_BL + buf * 64 * ASTR;
#pragma unroll
        for (int q = 0; q < 4; q++) {
            const float* v = (const float*)&aReg[q];
#pragma unroll
            for (int e = 0; e < 4; e++) {
                float x = v[e];
                unsigned hb = tf32_of(x);
                float hf = __uint_as_float(hb);
                unsigned lb = tf32_of(x - hf);
                Ah[arow * ASTR + acb + q * 4 + e] = hf;
                Al[arow * ASTR + acb + q * 4 + e] = __uint_as_float(lb);
            }
        }
#pragma unroll
        for (int q = 0; q < 2; q++) {
            const float* v = (const float*)&bReg[q];
#pragma unroll
            for (int e = 0; e < 4; e++) {
                float x = v[e];
                unsigned hb = tf32_of(x);
                float hf = __uint_as_float(hb);
                unsigned lb = tf32_of(x - hf);
                Bh[brow * ASTR + bcb + q * 4 + e] = hf;
                Bl[brow * ASTR + bcb + q * 4 + e] = __uint_as_float(lb);
            }
        }
    };

    ldg_chunk(0);
    sts_chunk(0);
    __syncthreads();

    const int NCHUNK = K / 32;
    for (int c = 0; c < NCHUNK; c++) {
        int buf = c & 1;
        if (c + 1 < NCHUNK) ldg_chunk((c + 1) * 32);

        const unsigned* Ah = (const unsigned*)(smf + IP_AH + buf * 128 * ASTR);
        const unsigned* Al = (const unsigned*)(smf + IP_AL + buf * 128 * ASTR);
        const unsigned* Bh = (const unsigned*)(smf + IP_BH + buf * 64 * ASTR);
        const unsigned* Bl = (const unsigned*)(smf + IP_BL + buf * 64 * ASTR);

#pragma unroll
        for (int ks = 0; ks < 4; ks++) {
            int kc = ks * 8;
            unsigned ah[2][4], al[2][4], bh[4][2], bl[4][2];
#pragma unroll
            for (int mt = 0; mt < 2; mt++) {
                int r0 = mrow0 + mt * 16 + (lane >> 2);
                int cc = kc + (lane & 3);
                ah[mt][0] = Ah[r0 * ASTR + cc];
                ah[mt][1] = Ah[(r0 + 8) * ASTR + cc];
                ah[mt][2] = Ah[r0 * ASTR + cc + 4];
                ah[mt][3] = Ah[(r0 + 8) * ASTR + cc + 4];
                al[mt][0] = Al[r0 * ASTR + cc];
                al[mt][1] = Al[(r0 + 8) * ASTR + cc];
                al[mt][2] = Al[r0 * ASTR + cc + 4];
                al[mt][3] = Al[(r0 + 8) * ASTR + cc + 4];
            }
#pragma unroll
            for (int nt = 0; nt < 4; nt++) {
                int n0 = ncol0 + nt * 8 + (lane >> 2);
                int kk = kc + (lane & 3);
                bh[nt][0] = Bh[n0 * ASTR + kk];
                bh[nt][1] = Bh[n0 * ASTR + kk + 4];
                bl[nt][0] = Bl[n0 * ASTR + kk];
                bl[nt][1] = Bl[n0 * ASTR + kk + 4];
            }
#pragma unroll
            for (int mt = 0; mt < 2; mt++)
#pragma unroll
                for (int nt = 0; nt < 4; nt++) {
                    mma_tf32(C[mt][nt], ah[mt], bh[nt]);
                    mma_tf32(C[mt][nt], al[mt], bh[nt]);
                    mma_tf32(C[mt][nt], ah[mt], bl[nt]);
                }
        }

        __syncthreads();
        if (c + 1 < NCHUNK) {
            sts_chunk(buf ^ 1);
            __syncthreads();
        }
    }

#pragma unroll
    for (int mt = 0; mt < 2; mt++) {
        int row = mbase + mrow0 + mt * 16 + (lane >> 2);
#pragma unroll
        for (int nt = 0; nt < 4; nt++) {
            int col = nbase + ncol0 + nt * 8 + (lane & 3) * 2;
            if (col < N) {
                g_zxbcdt[row * N + col]           = C[mt][nt][0];
                g_zxbcdt[row * N + col + 1]       = C[mt][nt][1];
                g_zxbcdt[(row + 8) * N + col]     = C[mt][nt][2];
                g_zxbcdt[(row + 8) * N + col + 1] = C[mt][nt][3];
            }
        }
    }
}

// ---------------- kernel 2: causal depthwise conv ----------------
__global__ __launch_bounds__(256) void conv_kernel(const float* __restrict__ conv_w,
                                                   const float* __restrict__ conv_b) {
    int idx = blockIdx.x * blockDim.x + threadIdx.x;
    if (idx >= BATCH * SEQLEN * CONVDIM) return;
    int c  = idx % CONVDIM;
    int bt = idx / CONVDIM;
    int t  = bt % SEQLEN;
    int b  = bt / SEQLEN;
    float accv = conv_b[c];
#pragma unroll
    for (int k = 0; k < DCONV; k++) {
        int tt = t + k - (DCONV - 1);
        if (tt >= 0)
            accv = fmaf(g_zxbcdt[(b * SEQLEN + tt) * DINPROJ + DSSM + c],
                        conv_w[c * DCONV + k], accv);
    }
    g_xbcconv[idx] = accv;
}

// ---------------- kernel 3: persistent scan, tensor-core phase A ----------------
__global__ __launch_bounds__(NTHR, 1) void scan_kernel(
    const float* __restrict__ dt_bias, const float* __restrict__ A_log,
    const float* __restrict__ D_param, const float* __restrict__ norm_w,
    float* __restrict__ out) {

    extern __shared__ float sm[];
    float* s_state = sm + SM_STATE;       // state[p][n], stride 132
    float* s_y     = sm + SM_Y;           // 8 warps x 512 partials
    float* s_bc    = sm + SM_BC;
    float* s_red   = sm + SM_RED;
    __shared__ unsigned s_base;

    const int tid  = threadIdx.x;
    const int cta  = blockIdx.x;
    const int lane = tid & 31;
    const int warp = tid >> 5;

    if (tid == 0) s_base = ld_acquire_u(&g_release);
    // zero Y frags (one word per thread across the grid)
    {
        int i = cta * NTHR + tid;
        if (i < 2 * 128 * 32 * 4) st_rlx_u(&g_yfrag[i], 0u);
    }
    for (int i = tid; i < 256 * 132; i += NTHR) s_state[i] = 0.0f;
    __syncthreads();
    unsigned epoch = s_base + 1;

    const int hasdt = (cta < NHEADS) ? 1 : 0;
    const int ntask = 18 + hasdt + 8;

    // ---- phase B constants ----
    const int h  = cta & 31;
    const int bg = cta >> 5;
    const int b_loc = tid >> 6;
    const int dd    = tid & 63;
    const int bglb  = bg * 4 + b_loc;
    const float Ah  = -expf(A_log[h]);
    const float dtb = dt_bias[h];
    const float Dh  = D_param[h];
    const float nw  = norm_w[h * HEADDIM + dd];

    // precompute this thread's Y-frag slot (t-invariant)
    int yk = h * HEADDIM + dd;
    int ys = yk >> 4;
    int yc = yk & 15;
    int yreg = ((yc >= 8) ? 2 : 0) + ((bglb >= 8) ? 1 : 0);
    int yln  = ((bglb & 7) << 2) | ((yc >> 1) & 3);
    int yhalf = yc & 1;
    unsigned short* yb16 = (unsigned short*)g_yfrag;
    int ywi = ((ys * 32 + yln) * 4 + yreg) * 2 + yhalf;   // hi plane; lo at +32768

    grid_barrier(cta, epoch++);

    for (int t = 0; t <= SEQLEN; t++) {
        // =================== phase A: D[16,32] = Y @ W^T (bf16 3-term MMA) ===========
        if (tid < 16) {
            const float* mp = g_mspart + tid * 32;
            float tot = 0.0f;
#pragma unroll
            for (int q = 0; q < 8; q++) {
                float4 v = ld_rlx_f4(mp + q * 4);
                tot += v.x + v.y + v.z + v.w;
            }
            s_red[tid] = rsqrtf(tot * (1.0f / (float)DSSM) + EPSV);
        }

        float acc[4][4];
#pragma unroll
        for (int nt = 0; nt < 4; nt++)
#pragma unroll
            for (int e = 0; e < 4; e++) acc[nt][e] = 0.0f;

#pragma unroll 4
        for (int sl = 0; sl < 16; sl++) {
            int s = (warp << 4) + sl;
            const uint4* wph = (const uint4*)(g_wfrag + ((size_t)(cta * 128 + s) * 2) * 256 + lane * 8);
            uint4 wh01 = wph[0];
            uint4 wh23 = wph[1];
            const uint4* wpl = (const uint4*)(g_wfrag + ((size_t)(cta * 128 + s) * 2 + 1) * 256 + lane * 8);
            uint4 wl01 = wpl[0];
            uint4 wl23 = wpl[1];
            F4U yh, yl;
            yh.f = ld_rlx_f4((const float*)(g_yfrag + (s * 32 + lane) * 4));
            yl.f = ld_rlx_f4((const float*)(g_yfrag + 16384 + (s * 32 + lane) * 4));

            mma_bf16(acc[0], yh.v, wh01.x, wh01.y);
            mma_bf16(acc[0], yl.v, wh01.x, wh01.y);
            mma_bf16(acc[0], yh.v, wl01.x, wl01.y);

            mma_bf16(acc[1], yh.v, wh01.z, wh01.w);
            mma_bf16(acc[1], yl.v, wh01.z, wh01.w);
            mma_bf16(acc[1], yh.v, wl01.z, wl01.w);

            mma_bf16(acc[2], yh.v, wh23.x, wh23.y);
            mma_bf16(acc[2], yl.v, wh23.x, wh23.y);
            mma_bf16(acc[2], yh.v, wl23.x, wl23.y);

            mma_bf16(acc[3], yh.v, wh23.z, wh23.w);
            mma_bf16(acc[3], yl.v, wh23.z, wh23.w);
            mma_bf16(acc[3], yh.v, wl23.z, wl23.w);
        }

        // store warp partials: D[b][r], b = lane>>2 (+8), r = nt*8 + (lane&3)*2 (+1)
        {
            int bq = lane >> 2;
            int c2 = (lane & 3) * 2;
            float* wp = s_y + warp * 512;
#pragma unroll
            for (int nt = 0; nt < 4; nt++) {
                *(float2*)(wp + bq * 32 + nt * 8 + c2)       = make_float2(acc[nt][0], acc[nt][1]);
                *(float2*)(wp + (bq + 8) * 32 + nt * 8 + c2) = make_float2(acc[nt][2], acc[nt][3]);
            }
        }
        __syncthreads();

        // reduce 8 warp planes, apply rb, dispatch
#pragma unroll
        for (int gi = 0; gi < 2; gi++) {
            int g = tid + gi * 256;
            int b = g >> 5;
            int r = g & 31;
            if (r >= ntask) continue;
            float sum = 0.0f;
#pragma unroll
            for (int w = 0; w < 8; w++) sum += s_y[w * 512 + g];
            float val = sum * s_red[b];
            if (r < 18) {
                if (t < SEQLEN) {
                    int idxv = cta * 18 + r;
                    float base = g_xbcconv[(b * SEQLEN + t) * CONVDIM + idxv];
                    st_rlx_f(&g_act[b * ACTDIM + idxv], silu_f(base + val));
                }
            } else if (hasdt && r == 18) {
                if (t < SEQLEN) {
                    float base = g_zxbcdt[(b * SEQLEN + t) * DINPROJ + (DSSM + CONVDIM) + cta];
                    st_rlx_f(&g_act[b * ACTDIM + CONVDIM + cta], silu_f(base + val));
                }
            } else {
                int idxv = cta * 8 + (r - 18 - hasdt);
                if (t >= 1) out[(b * SEQLEN + (t - 1)) * DMODEL + idxv] = val;
            }
        }

        if (t == SEQLEN) break;

        grid_barrier(cta, epoch++);   // act(t) visible

        // =================== phase B ===================
        for (int i = tid * 4; i < 1024; i += NTHR * 4) {
            int bl = i >> 8, k = i & 255;
            float4 v = ld_rlx_f4((const float*)&g_act[(bg * 4 + bl) * ACTDIM + DSSM + k]);
            *(float4*)(s_bc + i) = v;
        }
        __syncthreads();

        {
            float x   = ld_rlx_f(&g_act[bglb * ACTDIM + h * HEADDIM + dd]);
            float dtr = ld_rlx_f(&g_act[bglb * ACTDIM + CONVDIM + h]);
            float dt  = softplus_f(dtr + dtb);
            float dA  = expf(dt * Ah);
            float coef = dt * x;

            unsigned long long dA2 = pk2(dA, dA);
            unsigned long long cf2 = pk2(coef, coef);
            unsigned long long acc2 = 0ULL;

            const float* bvp = s_bc + b_loc * 256;
            float* sp = s_state + tid * 132;
#pragma unroll 4
            for (int n = 0; n < DSTATE; n += 4) {
                F4U sv, bv, cv;
                sv.f = *(float4*)(sp + n);
                bv.f = *(const float4*)(bvp + n);
                cv.f = *(const float4*)(bvp + 128 + n);
                sv.u[0] = fma2(sv.u[0], dA2, mul2(cf2, bv.u[0]));
                sv.u[1] = fma2(sv.u[1], dA2, mul2(cf2, bv.u[1]));
                acc2 = fma2(sv.u[0], cv.u[0], acc2);
                acc2 = fma2(sv.u[1], cv.u[1], acc2);
                *(float4*)(sp + n) = sv.f;
            }
            float alo, ahi;
            upk2(acc2, alo, ahi);
            float y = fmaf(Dh, x, alo + ahi);
            float z = g_zxbcdt[(bglb * SEQLEN + t) * DINPROJ + h * HEADDIM + dd];
            float g = y * silu_f(z);

            // write Y fragment (bf16 hi/lo) for phase A(t+1)
            float yv = g * nw;
            __nv_bfloat16 hb = __float2bfloat16(yv);
            float hf = __bfloat162float(hb);
            __nv_bfloat16 lb = __float2bfloat16(yv - hf);
            st_rlx_b16(yb16 + ywi, __bfloat16_as_ushort(hb));
            st_rlx_b16(yb16 + 32768 + ywi, __bfloat16_as_ushort(lb));

            float gsq = g * g;
#pragma unroll
            for (int off = 16; off > 0; off >>= 1)
                gsq += __shfl_xor_sync(0xffffffffu, gsq, off);
            if (lane == 0) s_red[16 + warp] = gsq;
        }
        __syncthreads();

        if (tid < 4) {
            float part = s_red[16 + 2 * tid] + s_red[16 + 2 * tid + 1];
            st_rlx_f(&g_mspart[(bg * 4 + tid) * 32 + h], part);
        }

        grid_barrier(cta, epoch++);   // yfrags + partials visible
    }
}

// ---------------- launcher ----------------
extern "C" void kernel_launch(void* const* d_in, const int* in_sizes, int n_in,
                              void* d_out, int out_size) {
    const float* u       = (const float*)d_in[0];
    const float* W_in    = (const float*)d_in[1];
    const float* conv_w  = (const float*)d_in[2];
    const float* conv_b  = (const float*)d_in[3];
    const float* W_rxbc  = (const float*)d_in[4];
    const float* W_rdt   = (const float*)d_in[5];
    const float* dt_bias = (const float*)d_in[6];
    const float* A_log   = (const float*)d_in[7];
    const float* D_param = (const float*)d_in[8];
    const float* norm_w  = (const float*)d_in[9];
    const float* W_out   = (const float*)d_in[10];
    float* out = (float*)d_out;

    static int attr_set = 0;
    const int SCAN_SMEM = SM_TOTALF * 4;
    const int IP_SMEM   = IP_TOTALF * 4;
    if (!attr_set) {
        cudaFuncSetAttribute(scan_kernel, cudaFuncAttributeMaxDynamicSharedMemorySize, SCAN_SMEM);
        cudaFuncSetAttribute(inproj_kernel, cudaFuncAttributeMaxDynamicSharedMemorySize, IP_SMEM);
        attr_set = 1;
    }

    wfrag_kernel<<<8192, 256>>>(W_rxbc, W_rdt, W_out);

    dim3 gIn((DINPROJ + 63) / 64, (BATCH * SEQLEN) / 128);
    inproj_kernel<<<gIn, 256, IP_SMEM>>>(u, W_in);

    int convN = BATCH * SEQLEN * CONVDIM;
    conv_kernel<<<(convN + 255) / 256, 256>>>(conv_w, conv_b);

    scan_kernel<<<NCTA, NTHR, SCAN_SMEM>>>(dt_bias, A_log, D_param, norm_w, out);
}

// round 10
// speedup vs baseline: 2.4994x; 1.1425x over previous
#include <cuda_runtime.h>
#include <cuda_bf16.h>
#include <math.h>

// ---------------- problem constants ----------------
#define BATCH     16
#define SEQLEN    512
#define DMODEL    1024
#define DSTATE    128
#define DCONV     4
#define HEADDIM   64
#define DSSM      2048
#define NHEADS    32
#define CONVDIM   2304            // DSSM + 2*DSTATE
#define DINPROJ   4384            // 2*DSSM + 2*DSTATE + NHEADS
#define ACTDIM    2336            // CONVDIM + NHEADS
#define NCTA      128
#define NTHR      512
#define EPSV      1e-5f

// scan SMEM layout (floats)
#define SM_STATE  0                        // 256*132 = 33792 (state[p][n], pad 132)
#define SM_Y      33792                    // 16*512 = 8192 (warp partials / scratch)
#define SM_BC     (33792 + 8192)           // 1024
#define SM_RED    (33792 + 8192 + 1024)    // 32
#define SM_TOTALF (33792 + 8192 + 1024 + 32)

// ---------------- device scratch ----------------
__device__ float g_zxbcdt[BATCH * SEQLEN * DINPROJ];
__device__ float g_xbcconv[BATCH * SEQLEN * CONVDIM];
__device__ float g_act[BATCH * ACTDIM];
__device__ float g_mspart[BATCH * 32];          // per (batch, head) sum of g^2
__device__ unsigned g_arrive[NCTA * 32];        // padded per-CTA epoch flags (monotonic)
__device__ unsigned g_release;                  // epoch base carrier across replays
// W fragments: [cta][s(128)][hilo(2)][lane(32)][nt(4)][b0,b1] as u32 -> 32 MB
__device__ unsigned g_wfrag[128 * 128 * 2 * 256];
// Y fragments: [hilo][s(128)][lane(32)][reg(4)] as u32 (bf16x2) -> 128 KB
__device__ unsigned g_yfrag[2 * 128 * 32 * 4];

// ---------------- helpers ----------------
__device__ __forceinline__ float silu_f(float v) { return v / (1.0f + expf(-v)); }
__device__ __forceinline__ float softplus_f(float v) { return (v > 20.0f) ? v : log1pf(expf(v)); }

__device__ __forceinline__ void upk2(unsigned long long v, float& lo, float& hi) {
    unsigned a, b;
    asm("mov.b64 {%0, %1}, %2;" : "=r"(a), "=r"(b) : "l"(v));
    lo = __uint_as_float(a); hi = __uint_as_float(b);
}
__device__ __forceinline__ unsigned long long pk2(float lo, float hi) {
    unsigned long long r;
    asm("mov.b64 %0, {%1, %2};" : "=l"(r) : "r"(__float_as_uint(lo)), "r"(__float_as_uint(hi)));
    return r;
}
__device__ __forceinline__ unsigned long long fma2(unsigned long long a, unsigned long long b,
                                                   unsigned long long c) {
    unsigned long long d;
    asm("fma.rn.f32x2 %0, %1, %2, %3;" : "=l"(d) : "l"(a), "l"(b), "l"(c));
    return d;
}
__device__ __forceinline__ unsigned long long mul2(unsigned long long a, unsigned long long b) {
    unsigned long long d;
    asm("mul.rn.f32x2 %0, %1, %2;" : "=l"(d) : "l"(a), "l"(b));
    return d;
}
__device__ __forceinline__ unsigned tf32_of(float x) {
    unsigned r;
    asm("cvt.rna.tf32.f32 %0, %1;" : "=r"(r) : "f"(x));
    return r;
}

// ---- strong (L2-coherent) memory ops ----
__device__ __forceinline__ void st_release_u(unsigned* p, unsigned v) {
    asm volatile("st.release.gpu.global.u32 [%0], %1;" :: "l"(p), "r"(v) : "memory");
}
__device__ __forceinline__ unsigned ld_acquire_u(const unsigned* p) {
    unsigned v;
    asm volatile("ld.acquire.gpu.global.u32 %0, [%1];" : "=r"(v) : "l"(p) : "memory");
    return v;
}
__device__ __forceinline__ float ld_rlx_f(const float* p) {
    float v;
    asm volatile("ld.relaxed.gpu.global.f32 %0, [%1];" : "=f"(v) : "l"(p) : "memory");
    return v;
}
__device__ __forceinline__ void st_rlx_f(float* p, float v) {
    asm volatile("st.relaxed.gpu.global.f32 [%0], %1;" :: "l"(p), "f"(v) : "memory");
}
__device__ __forceinline__ void st_rlx_u(unsigned* p, unsigned v) {
    asm volatile("st.relaxed.gpu.global.u32 [%0], %1;" :: "l"(p), "r"(v) : "memory");
}
__device__ __forceinline__ void st_rlx_b16(unsigned short* p, unsigned short v) {
    asm volatile("st.relaxed.gpu.global.b16 [%0], %1;" :: "l"(p), "h"(v) : "memory");
}
__device__ __forceinline__ float4 ld_rlx_f4(const float* p) {
    float4 v;
    asm volatile("ld.relaxed.gpu.global.v4.f32 {%0,%1,%2,%3}, [%4];"
                 : "=f"(v.x), "=f"(v.y), "=f"(v.z), "=f"(v.w) : "l"(p) : "memory");
    return v;
}

union F4U { float4 f; unsigned long long u[2]; unsigned v[4]; };

// FLAT single-hop grid barrier: every CTA's first 128 threads poll all flags.
__device__ __forceinline__ void grid_barrier(int cta, unsigned epoch) {
    __syncthreads();
    if (threadIdx.x == 0) st_release_u(&g_arrive[cta * 32], epoch);
    if (threadIdx.x < 128) {
        while (ld_acquire_u(&g_arrive[threadIdx.x * 32]) < epoch) { }
    }
    __syncthreads();
}

// bf16 MMA: D[16x8] += A[16x16] * B[16x8]
__device__ __forceinline__ void mma_bf16(float* d, const unsigned* a, unsigned b0, unsigned b1) {
    asm volatile(
        "mma.sync.aligned.m16n8k16.row.col.f32.bf16.bf16.f32 "
        "{%0,%1,%2,%3}, {%4,%5,%6,%7}, {%8,%9}, {%0,%1,%2,%3};"
        : "+f"(d[0]), "+f"(d[1]), "+f"(d[2]), "+f"(d[3])
        : "r"(a[0]), "r"(a[1]), "r"(a[2]), "r"(a[3]), "r"(b0), "r"(b1));
}

// ---------------- kernel 0: precompute W fragments (bf16 hi/lo split) ----------------
__global__ __launch_bounds__(256) void wfrag_kernel(const float* __restrict__ W_rxbc,
                                                    const float* __restrict__ W_rdt,
                                                    const float* __restrict__ W_out) {
    int idx = blockIdx.x * 256 + threadIdx.x;      // < 128*128*32*4
    int nt   = idx & 3;
    int lane = (idx >> 2) & 31;
    int s    = (idx >> 7) & 127;
    int cta  = idx >> 14;
    int hasdt = (cta < NHEADS) ? 1 : 0;
    int ntask = 18 + hasdt + 8;
    int n_local = nt * 8 + (lane >> 2);
    int k0 = s * 16 + (lane & 3) * 2;

    float w00 = 0.f, w01 = 0.f, w10 = 0.f, w11 = 0.f;
    if (n_local < ntask) {
        const float* p;
        if (n_local < 18) p = W_rxbc + (size_t)(cta * 18 + n_local) * DSSM;
        else if (hasdt && n_local == 18) p = W_rdt + (size_t)cta * DSSM;
        else p = W_out + (size_t)(cta * 8 + n_local - 18 - hasdt) * DSSM;
        w00 = p[k0]; w01 = p[k0 + 1]; w10 = p[k0 + 8]; w11 = p[k0 + 9];
    }

    unsigned short h00, l00, h01, l01, h10, l10, h11, l11;
    {
        __nv_bfloat16 h;
        h = __float2bfloat16(w00); h00 = __bfloat16_as_ushort(h);
        l00 = __bfloat16_as_ushort(__float2bfloat16(w00 - __bfloat162float(h)));
        h = __float2bfloat16(w01); h01 = __bfloat16_as_ushort(h);
        l01 = __bfloat16_as_ushort(__float2bfloat16(w01 - __bfloat162float(h)));
        h = __float2bfloat16(w10); h10 = __bfloat16_as_ushort(h);
        l10 = __bfloat16_as_ushort(__float2bfloat16(w10 - __bfloat162float(h)));
        h = __float2bfloat16(w11); h11 = __bfloat16_as_ushort(h);
        l11 = __bfloat16_as_ushort(__float2bfloat16(w11 - __bfloat162float(h)));
    }

    size_t basehi = ((size_t)(cta * 128 + s) * 2) * 256 + lane * 8 + nt * 2;
    g_wfrag[basehi]       = (unsigned)h00 | ((unsigned)h01 << 16);
    g_wfrag[basehi + 1]   = (unsigned)h10 | ((unsigned)h11 << 16);
    g_wfrag[basehi + 256] = (unsigned)l00 | ((unsigned)l01 << 16);
    g_wfrag[basehi + 257] = (unsigned)l10 | ((unsigned)l11 << 16);
}

// ---------------- kernel 1: in_proj GEMM, tf32 mma (unchanged R8) --------
#define ASTR 36
#define IP_AH 0
#define IP_AL (2 * 128 * ASTR)
#define IP_BH (4 * 128 * ASTR)
#define IP_BL (4 * 128 * ASTR + 2 * 64 * ASTR)
#define IP_TOTALF (4 * 128 * ASTR + 4 * 64 * ASTR)

__device__ __forceinline__ void mma_tf32(float* d, const unsigned* a, const unsigned* b) {
    asm volatile(
        "mma.sync.aligned.m16n8k8.row.col.f32.tf32.tf32.f32 "
        "{%0,%1,%2,%3}, {%4,%5,%6,%7}, {%8,%9}, {%0,%1,%2,%3};"
        : "+f"(d[0]), "+f"(d[1]), "+f"(d[2]), "+f"(d[3])
        : "r"(a[0]), "r"(a[1]), "r"(a[2]), "r"(a[3]), "r"(b[0]), "r"(b[1]));
}

__global__ __launch_bounds__(256) void inproj_kernel(const float* __restrict__ U,
                                                     const float* __restrict__ Win) {
    extern __shared__ float smf[];
    const int N = DINPROJ;
    const int K = DMODEL;

    const int tid  = threadIdx.x;
    const int lane = tid & 31;
    const int warp = tid >> 5;
    const int mbase = blockIdx.y * 128;
    const int nbase = blockIdx.x * 64;
    const int mrow0 = (warp & 3) * 32;
    const int ncol0 = (warp >> 2) * 32;

    const int arow = tid >> 1;
    const int acb  = (tid & 1) * 16;
    const int brow = tid >> 2;
    const int bcb  = (tid & 3) * 8;

    float C[2][4][4];
#pragma unroll
    for (int mt = 0; mt < 2; mt++)
#pragma unroll
        for (int nt = 0; nt < 4; nt++)
#pragma unroll
            for (int e = 0; e < 4; e++) C[mt][nt][e] = 0.0f;

    float4 aReg[4];
    float4 bReg[2];

    auto ldg_chunk = [&](int k0) {
#pragma unroll
        for (int q = 0; q < 4; q++)
            aReg[q] = *(const float4*)(U + (mbase + arow) * K + k0 + acb + q * 4);
        if (nbase + brow < N) {
#pragma unroll
            for (int q = 0; q < 2; q++)
                bReg[q] = *(const float4*)(Win + (nbase + brow) * K + k0 + bcb + q * 4);
        } else {
            bReg[0] = make_float4(0.f, 0.f, 0.f, 0.f);
            bReg[1] = make_float4(0.f, 0.f, 0.f, 0.f);
        }
    };

    auto sts_chunk = [&](int buf) {
        float* Ah = smf + IP_AH + buf * 128 * ASTR;
        float* Al = smf + IP_AL + buf * 128 * ASTR;
        float* Bh = smf + IP_BH + buf * 64 * ASTR;
        float* Bl = smf + IP_BL + buf * 64 * ASTR;
#pragma unroll
        for (int q = 0; q < 4; q++) {
            const float* v = (const float*)&aReg[q];
#pragma unroll
            for (int e = 0; e < 4; e++) {
                float x = v[e];
                unsigned hb = tf32_of(x);
                float hf = __uint_as_float(hb);
                unsigned lb = tf32_of(x - hf);
                Ah[arow * ASTR + acb + q * 4 + e] = hf;
                Al[arow * ASTR + acb + q * 4 + e] = __uint_as_float(lb);
            }
        }
#pragma unroll
        for (int q = 0; q < 2; q++) {
            const float* v = (const float*)&bReg[q];
#pragma unroll
            for (int e = 0; e < 4; e++) {
                float x = v[e];
                unsigned hb = tf32_of(x);
                float hf = __uint_as_float(hb);
                unsigned lb = tf32_of(x - hf);
                Bh[brow * ASTR + bcb + q * 4 + e] = hf;
                Bl[brow * ASTR + bcb + q * 4 + e] = __uint_as_float(lb);
            }
        }
    };

    ldg_chunk(0);
    sts_chunk(0);
    __syncthreads();

    const int NCHUNK = K / 32;
    for (int c = 0; c < NCHUNK; c++) {
        int buf = c & 1;
        if (c + 1 < NCHUNK) ldg_chunk((c + 1) * 32);

        const unsigned* Ah = (const unsigned*)(smf + IP_AH + buf * 128 * ASTR);
        const unsigned* Al = (const unsigned*)(smf + IP_AL + buf * 128 * ASTR);
        const unsigned* Bh = (const unsigned*)(smf + IP_BH + buf * 64 * ASTR);
        const unsigned* Bl = (const unsigned*)(smf + IP_BL + buf * 64 * ASTR);

#pragma unroll
        for (int ks = 0; ks < 4; ks++) {
            int kc = ks * 8;
            unsigned ah[2][4], al[2][4], bh[4][2], bl[4][2];
#pragma unroll
            for (int mt = 0; mt < 2; mt++) {
                int r0 = mrow0 + mt * 16 + (lane >> 2);
                int cc = kc + (lane & 3);
                ah[mt][0] = Ah[r0 * ASTR + cc];
                ah[mt][1] = Ah[(r0 + 8) * ASTR + cc];
                ah[mt][2] = Ah[r0 * ASTR + cc + 4];
                ah[mt][3] = Ah[(r0 + 8) * ASTR + cc + 4];
                al[mt][0] = Al[r0 * ASTR + cc];
                al[mt][1] = Al[(r0 + 8) * ASTR + cc];
                al[mt][2] = Al[r0 * ASTR + cc + 4];
                al[mt][3] = Al[(r0 + 8) * ASTR + cc + 4];
            }
#pragma unroll
            for (int nt = 0; nt < 4; nt++) {
                int n0 = ncol0 + nt * 8 + (lane >> 2);
                int kk = kc + (lane & 3);
                bh[nt][0] = Bh[n0 * ASTR + kk];
                bh[nt][1] = Bh[n0 * ASTR + kk + 4];
                bl[nt][0] = Bl[n0 * ASTR + kk];
                bl[nt][1] = Bl[n0 * ASTR + kk + 4];
            }
#pragma unroll
            for (int mt = 0; mt < 2; mt++)
#pragma unroll
                for (int nt = 0; nt < 4; nt++) {
                    mma_tf32(C[mt][nt], ah[mt], bh[nt]);
                    mma_tf32(C[mt][nt], al[mt], bh[nt]);
                    mma_tf32(C[mt][nt], ah[mt], bl[nt]);
                }
        }

        __syncthreads();
        if (c + 1 < NCHUNK) {
            sts_chunk(buf ^ 1);
            __syncthreads();
        }
    }

#pragma unroll
    for (int mt = 0; mt < 2; mt++) {
        int row = mbase + mrow0 + mt * 16 + (lane >> 2);
#pragma unroll
        for (int nt = 0; nt < 4; nt++) {
            int col = nbase + ncol0 + nt * 8 + (lane & 3) * 2;
            if (col < N) {
                g_zxbcdt[row * N + col]           = C[mt][nt][0];
                g_zxbcdt[row * N + col + 1]       = C[mt][nt][1];
                g_zxbcdt[(row + 8) * N + col]     = C[mt][nt][2];
                g_zxbcdt[(row + 8) * N + col + 1] = C[mt][nt][3];
            }
        }
    }
}

// ---------------- kernel 2: causal depthwise conv ----------------
__global__ __launch_bounds__(256) void conv_kernel(const float* __restrict__ conv_w,
                                                   const float* __restrict__ conv_b) {
    int idx = blockIdx.x * blockDim.x + threadIdx.x;
    if (idx >= BATCH * SEQLEN * CONVDIM) return;
    int c  = idx % CONVDIM;
    int bt = idx / CONVDIM;
    int t  = bt % SEQLEN;
    int b  = bt / SEQLEN;
    float accv = conv_b[c];
#pragma unroll
    for (int k = 0; k < DCONV; k++) {
        int tt = t + k - (DCONV - 1);
        if (tt >= 0)
            accv = fmaf(g_zxbcdt[(b * SEQLEN + tt) * DINPROJ + DSSM + c],
                        conv_w[c * DCONV + k], accv);
    }
    g_xbcconv[idx] = accv;
}

// ---------------- kernel 3: persistent scan, 512 threads ----------------
__global__ __launch_bounds__(NTHR, 1) void scan_kernel(
    const float* __restrict__ dt_bias, const float* __restrict__ A_log,
    const float* __restrict__ D_param, const float* __restrict__ norm_w,
    float* __restrict__ out) {

    extern __shared__ float sm[];
    float* s_state = sm + SM_STATE;       // state[p][n], p = b_loc*64+dd, stride 132
    float* s_y     = sm + SM_Y;           // 16 warps x 512 partials / phase-B scratch
    float* s_bc    = sm + SM_BC;
    float* s_red   = sm + SM_RED;
    __shared__ unsigned s_base;

    const int tid  = threadIdx.x;
    const int cta  = blockIdx.x;
    const int lane = tid & 31;
    const int warp = tid >> 5;

    if (tid == 0) s_base = ld_acquire_u(&g_release);
    {
        int i = cta * NTHR + tid;
        if (i < 2 * 128 * 32 * 4) st_rlx_u(&g_yfrag[i], 0u);
    }
    for (int i = tid; i < 256 * 132; i += NTHR) s_state[i] = 0.0f;
    __syncthreads();
    unsigned epoch = s_base + 1;

    const int hasdt = (cta < NHEADS) ? 1 : 0;
    const int ntask = 18 + hasdt + 8;

    // ---- phase B mapping: p = tid & 255, half = tid >> 8 ----
    const int p     = tid & 255;
    const int half  = tid >> 8;
    const int h  = cta & 31;
    const int bg = cta >> 5;
    const int b_loc = p >> 6;
    const int dd    = p & 63;
    const int bglb  = bg * 4 + b_loc;
    const float Ah  = -expf(A_log[h]);
    const float dtb = dt_bias[h];
    const float Dh  = D_param[h];
    const float nw  = norm_w[h * HEADDIM + dd];
    const int n0    = half * 64;

    // Y-frag slot (based on p; only half==0 writes)
    int yk = h * HEADDIM + dd;
    int ys = yk >> 4;
    int yc = yk & 15;
    int yreg = ((yc >= 8) ? 2 : 0) + ((bglb >= 8) ? 1 : 0);
    int yln  = ((bglb & 7) << 2) | ((yc >> 1) & 3);
    int yhalf = yc & 1;
    unsigned short* yb16 = (unsigned short*)g_yfrag;
    int ywi = ((ys * 32 + yln) * 4 + yreg) * 2 + yhalf;

    grid_barrier(cta, epoch++);

    for (int t = 0; t <= SEQLEN; t++) {
        // =================== phase A: D[16,32] = Y @ W^T, K split 16 ways ===========
        if (tid < 16) {
            const float* mp = g_mspart + tid * 32;
            float tot = 0.0f;
#pragma unroll
            for (int q = 0; q < 8; q++) {
                float4 v = ld_rlx_f4(mp + q * 4);
                tot += v.x + v.y + v.z + v.w;
            }
            s_red[tid] = rsqrtf(tot * (1.0f / (float)DSSM) + EPSV);
        }

        float acc[4][4];
#pragma unroll
        for (int nt = 0; nt < 4; nt++)
#pragma unroll
            for (int e = 0; e < 4; e++) acc[nt][e] = 0.0f;

#pragma unroll 4
        for (int sl = 0; sl < 8; sl++) {
            int s = (warp << 3) + sl;
            const uint4* wph = (const uint4*)(g_wfrag + ((size_t)(cta * 128 + s) * 2) * 256 + lane * 8);
            uint4 wh01 = wph[0];
            uint4 wh23 = wph[1];
            const uint4* wpl = (const uint4*)(g_wfrag + ((size_t)(cta * 128 + s) * 2 + 1) * 256 + lane * 8);
            uint4 wl01 = wpl[0];
            uint4 wl23 = wpl[1];
            F4U yh, yl;
            yh.f = ld_rlx_f4((const float*)(g_yfrag + (s * 32 + lane) * 4));
            yl.f = ld_rlx_f4((const float*)(g_yfrag + 16384 + (s * 32 + lane) * 4));

            mma_bf16(acc[0], yh.v, wh01.x, wh01.y);
            mma_bf16(acc[0], yl.v, wh01.x, wh01.y);
            mma_bf16(acc[0], yh.v, wl01.x, wl01.y);

            mma_bf16(acc[1], yh.v, wh01.z, wh01.w);
            mma_bf16(acc[1], yl.v, wh01.z, wh01.w);
            mma_bf16(acc[1], yh.v, wl01.z, wl01.w);

            mma_bf16(acc[2], yh.v, wh23.x, wh23.y);
            mma_bf16(acc[2], yl.v, wh23.x, wh23.y);
            mma_bf16(acc[2], yh.v, wl23.x, wl23.y);

            mma_bf16(acc[3], yh.v, wh23.z, wh23.w);
            mma_bf16(acc[3], yl.v, wh23.z, wh23.w);
            mma_bf16(acc[3], yh.v, wl23.z, wl23.w);
        }

        {
            int bq = lane >> 2;
            int c2 = (lane & 3) * 2;
            float* wp = s_y + warp * 512;
#pragma unroll
            for (int nt = 0; nt < 4; nt++) {
                *(float2*)(wp + bq * 32 + nt * 8 + c2)       = make_float2(acc[nt][0], acc[nt][1]);
                *(float2*)(wp + (bq + 8) * 32 + nt * 8 + c2) = make_float2(acc[nt][2], acc[nt][3]);
            }
        }
        __syncthreads();

        // reduce 16 warp planes; one group per thread
        {
            int g = tid;
            int b = g >> 5;
            int r = g & 31;
            if (r < ntask) {
                float sum = 0.0f;
#pragma unroll
                for (int w = 0; w < 16; w++) sum += s_y[w * 512 + g];
                float val = sum * s_red[b];
                if (r < 18) {
                    if (t < SEQLEN) {
                        int idxv = cta * 18 + r;
                        float base = g_xbcconv[(b * SEQLEN + t) * CONVDIM + idxv];
                        st_rlx_f(&g_act[b * ACTDIM + idxv], silu_f(base + val));
                    }
                } else if (hasdt && r == 18) {
                    if (t < SEQLEN) {
                        float base = g_zxbcdt[(b * SEQLEN + t) * DINPROJ + (DSSM + CONVDIM) + cta];
                        st_rlx_f(&g_act[b * ACTDIM + CONVDIM + cta], silu_f(base + val));
                    }
                } else {
                    int idxv = cta * 8 + (r - 18 - hasdt);
                    if (t >= 1) out[(b * SEQLEN + (t - 1)) * DMODEL + idxv] = val;
                }
            }
        }

        if (t == SEQLEN) break;

        grid_barrier(cta, epoch++);   // act(t) visible

        // =================== phase B (n-range split across halves) ===================
        for (int i = tid * 4; i < 1024; i += NTHR * 4) {
            int bl = i >> 8, k = i & 255;
            float4 v = ld_rlx_f4((const float*)&g_act[(bg * 4 + bl) * ACTDIM + DSSM + k]);
            *(float4*)(s_bc + i) = v;
        }
        __syncthreads();

        float x, dt_v, g;
        {
            x = ld_rlx_f(&g_act[bglb * ACTDIM + h * HEADDIM + dd]);
            float dtr = ld_rlx_f(&g_act[bglb * ACTDIM + CONVDIM + h]);
            dt_v = softplus_f(dtr + dtb);
            float dA  = expf(dt_v * Ah);
            float coef = dt_v * x;

            unsigned long long dA2 = pk2(dA, dA);
            unsigned long long cf2 = pk2(coef, coef);
            unsigned long long acc2 = 0ULL;

            const float* bvp = s_bc + b_loc * 256 + n0;
            const float* cvp = s_bc + b_loc * 256 + 128 + n0;
            float* sp = s_state + p * 132 + n0;
#pragma unroll 4
            for (int n = 0; n < 64; n += 4) {
                F4U sv, bv, cv;
                sv.f = *(float4*)(sp + n);
                bv.f = *(const float4*)(bvp + n);
                cv.f = *(const float4*)(cvp + n);
                sv.u[0] = fma2(sv.u[0], dA2, mul2(cf2, bv.u[0]));
                sv.u[1] = fma2(sv.u[1], dA2, mul2(cf2, bv.u[1]));
                acc2 = fma2(sv.u[0], cv.u[0], acc2);
                acc2 = fma2(sv.u[1], cv.u[1], acc2);
                *(float4*)(sp + n) = sv.f;
            }
            float alo, ahi;
            upk2(acc2, alo, ahi);
            s_y[tid] = alo + ahi;     // partial dot over this half's n-range
        }
        __syncthreads();

        if (half == 0) {
            float accv = s_y[tid] + s_y[tid + 256];
            float y = fmaf(Dh, x, accv);
            float z = g_zxbcdt[(bglb * SEQLEN + t) * DINPROJ + h * HEADDIM + dd];
            g = y * silu_f(z);

            float yv = g * nw;
            __nv_bfloat16 hb = __float2bfloat16(yv);
            float hf = __bfloat162float(hb);
            __nv_bfloat16 lb = __float2bfloat16(yv - hf);
            st_rlx_b16(yb16 + ywi, __bfloat16_as_ushort(hb));
            st_rlx_b16(yb16 + 32768 + ywi, __bfloat16_as_ushort(lb));

            float gsq = g * g;
#pragma unroll
            for (int off = 16; off > 0; off >>= 1)
                gsq += __shfl_xor_sync(0xffffffffu, gsq, off);
            if (lane == 0) s_red[16 + warp] = gsq;   // warps 0..7
        }
        __syncthreads();

        if (tid < 4) {
            float part = s_red[16 + 2 * tid] + s_red[16 + 2 * tid + 1];
            st_rlx_f(&g_mspart[(bg * 4 + tid) * 32 + h], part);
        }

        grid_barrier(cta, epoch++);   // yfrags + partials visible
    }
}

// ---------------- launcher ----------------
extern "C" void kernel_launch(void* const* d_in, const int* in_sizes, int n_in,
                              void* d_out, int out_size) {
    const float* u       = (const float*)d_in[0];
    const float* W_in    = (const float*)d_in[1];
    const float* conv_w  = (const float*)d_in[2];
    const float* conv_b  = (const float*)d_in[3];
    const float* W_rxbc  = (const float*)d_in[4];
    const float* W_rdt   = (const float*)d_in[5];
    const float* dt_bias = (const float*)d_in[6];
    const float* A_log   = (const float*)d_in[7];
    const float* D_param = (const float*)d_in[8];
    const float* norm_w  = (const float*)d_in[9];
    const float* W_out   = (const float*)d_in[10];
    float* out = (float*)d_out;

    static int attr_set = 0;
    const int SCAN_SMEM = SM_TOTALF * 4;
    const int IP_SMEM   = IP_TOTALF * 4;
    if (!attr_set) {
        cudaFuncSetAttribute(scan_kernel, cudaFuncAttributeMaxDynamicSharedMemorySize, SCAN_SMEM);
        cudaFuncSetAttribute(inproj_kernel, cudaFuncAttributeMaxDynamicSharedMemorySize, IP_SMEM);
        attr_set = 1;
    }

    wfrag_kernel<<<8192, 256>>>(W_rxbc, W_rdt, W_out);

    dim3 gIn((DINPROJ + 63) / 64, (BATCH * SEQLEN) / 128);
    inproj_kernel<<<gIn, 256, IP_SMEM>>>(u, W_in);

    int convN = BATCH * SEQLEN * CONVDIM;
    conv_kernel<<<(convN + 255) / 256, 256>>>(conv_w, conv_b);

    scan_kernel<<<NCTA, NTHR, SCAN_SMEM>>>(dt_bias, A_log, D_param, norm_w, out);
}

// round 11
// speedup vs baseline: 2.6108x; 1.0446x over previous
#include <cuda_runtime.h>
#include <cuda_bf16.h>
#include <math.h>

// ---------------- problem constants ----------------
#define BATCH     16
#define SEQLEN    512
#define DMODEL    1024
#define DSTATE    128
#define DCONV     4
#define HEADDIM   64
#define DSSM      2048
#define NHEADS    32
#define CONVDIM   2304            // DSSM + 2*DSTATE
#define DINPROJ   4384            // 2*DSSM + 2*DSTATE + NHEADS
#define ACTDIM    2336            // CONVDIM + NHEADS
#define NCTA      128
#define NTHR      512
#define EPSV      1e-5f

// scan SMEM layout (floats)
#define SM_STATE  0                        // 256*132 = 33792 (state[p][n], pad 132)
#define SM_Y      33792                    // 16*512 = 8192 (warp partials / scratch)
#define SM_BC     (33792 + 8192)           // 1024
#define SM_RED    (33792 + 8192 + 1024)    // 32
#define SM_TOTALF (33792 + 8192 + 1024 + 32)

// ---------------- device scratch ----------------
__device__ float g_zxbcdt[BATCH * SEQLEN * DINPROJ];
__device__ float g_xbcconv[BATCH * SEQLEN * CONVDIM];
__device__ float g_act[BATCH * ACTDIM];
__device__ float g_mspart[BATCH * 32];          // per (batch, head) sum of g^2
__device__ unsigned g_arrive[NCTA * 32];        // padded per-CTA epoch flags (monotonic)
__device__ unsigned g_release;                  // epoch base carrier across replays
// W fragments: [cta][s(128)][hilo(2)][lane(32)][nt(4)][b0,b1] as u32 -> 32 MB
__device__ unsigned g_wfrag[128 * 128 * 2 * 256];
// Y fragments: [hilo][s(128)][lane(32)][reg(4)] as u32 (bf16x2) -> 128 KB
__device__ unsigned g_yfrag[2 * 128 * 32 * 4];

// ---------------- helpers ----------------
__device__ __forceinline__ float silu_f(float v) { return v / (1.0f + expf(-v)); }
__device__ __forceinline__ float softplus_f(float v) { return (v > 20.0f) ? v : log1pf(expf(v)); }

__device__ __forceinline__ void upk2(unsigned long long v, float& lo, float& hi) {
    unsigned a, b;
    asm("mov.b64 {%0, %1}, %2;" : "=r"(a), "=r"(b) : "l"(v));
    lo = __uint_as_float(a); hi = __uint_as_float(b);
}
__device__ __forceinline__ unsigned long long pk2(float lo, float hi) {
    unsigned long long r;
    asm("mov.b64 %0, {%1, %2};" : "=l"(r) : "r"(__float_as_uint(lo)), "r"(__float_as_uint(hi)));
    return r;
}
__device__ __forceinline__ unsigned long long fma2(unsigned long long a, unsigned long long b,
                                                   unsigned long long c) {
    unsigned long long d;
    asm("fma.rn.f32x2 %0, %1, %2, %3;" : "=l"(d) : "l"(a), "l"(b), "l"(c));
    return d;
}
__device__ __forceinline__ unsigned long long mul2(unsigned long long a, unsigned long long b) {
    unsigned long long d;
    asm("mul.rn.f32x2 %0, %1, %2;" : "=l"(d) : "l"(a), "l"(b));
    return d;
}
__device__ __forceinline__ unsigned tf32_of(float x) {
    unsigned r;
    asm("cvt.rna.tf32.f32 %0, %1;" : "=r"(r) : "f"(x));
    return r;
}

// ---- strong (L2-coherent) memory ops ----
__device__ __forceinline__ void st_release_u(unsigned* p, unsigned v) {
    asm volatile("st.release.gpu.global.u32 [%0], %1;" :: "l"(p), "r"(v) : "memory");
}
__device__ __forceinline__ unsigned ld_acquire_u(const unsigned* p) {
    unsigned v;
    asm volatile("ld.acquire.gpu.global.u32 %0, [%1];" : "=r"(v) : "l"(p) : "memory");
    return v;
}
__device__ __forceinline__ float ld_rlx_f(const float* p) {
    float v;
    asm volatile("ld.relaxed.gpu.global.f32 %0, [%1];" : "=f"(v) : "l"(p) : "memory");
    return v;
}
__device__ __forceinline__ void st_rlx_f(float* p, float v) {
    asm volatile("st.relaxed.gpu.global.f32 [%0], %1;" :: "l"(p), "f"(v) : "memory");
}
__device__ __forceinline__ void st_rlx_u(unsigned* p, unsigned v) {
    asm volatile("st.relaxed.gpu.global.u32 [%0], %1;" :: "l"(p), "r"(v) : "memory");
}
__device__ __forceinline__ void st_rlx_b16(unsigned short* p, unsigned short v) {
    asm volatile("st.relaxed.gpu.global.b16 [%0], %1;" :: "l"(p), "h"(v) : "memory");
}
__device__ __forceinline__ float2 ld_rlx_f2(const float* p) {
    float2 v;
    asm volatile("ld.relaxed.gpu.global.v2.f32 {%0,%1}, [%2];"
                 : "=f"(v.x), "=f"(v.y) : "l"(p) : "memory");
    return v;
}
__device__ __forceinline__ float4 ld_rlx_f4(const float* p) {
    float4 v;
    asm volatile("ld.relaxed.gpu.global.v4.f32 {%0,%1,%2,%3}, [%4];"
                 : "=f"(v.x), "=f"(v.y), "=f"(v.z), "=f"(v.w) : "l"(p) : "memory");
    return v;
}

union F4U { float4 f; unsigned long long u[2]; unsigned v[4]; };

// FLAT single-hop grid barrier: every CTA's first 128 threads poll all flags.
__device__ __forceinline__ void grid_barrier(int cta, unsigned epoch) {
    __syncthreads();
    if (threadIdx.x == 0) st_release_u(&g_arrive[cta * 32], epoch);
    if (threadIdx.x < 128) {
        while (ld_acquire_u(&g_arrive[threadIdx.x * 32]) < epoch) { }
    }
    __syncthreads();
}

// bf16 MMA: D[16x8] += A[16x16] * B[16x8]  (NON-volatile: let ptxas schedule)
__device__ __forceinline__ void mma_bf16(float* d, const unsigned* a, unsigned b0, unsigned b1) {
    asm("mma.sync.aligned.m16n8k16.row.col.f32.bf16.bf16.f32 "
        "{%0,%1,%2,%3}, {%4,%5,%6,%7}, {%8,%9}, {%0,%1,%2,%3};"
        : "+f"(d[0]), "+f"(d[1]), "+f"(d[2]), "+f"(d[3])
        : "r"(a[0]), "r"(a[1]), "r"(a[2]), "r"(a[3]), "r"(b0), "r"(b1));
}

// ---------------- kernel 0: precompute W fragments (bf16 hi/lo split) ----------------
__global__ __launch_bounds__(256) void wfrag_kernel(const float* __restrict__ W_rxbc,
                                                    const float* __restrict__ W_rdt,
                                                    const float* __restrict__ W_out) {
    int idx = blockIdx.x * 256 + threadIdx.x;      // < 128*128*32*4
    int nt   = idx & 3;
    int lane = (idx >> 2) & 31;
    int s    = (idx >> 7) & 127;
    int cta  = idx >> 14;
    int hasdt = (cta < NHEADS) ? 1 : 0;
    int ntask = 18 + hasdt + 8;
    int n_local = nt * 8 + (lane >> 2);
    int k0 = s * 16 + (lane & 3) * 2;

    float w00 = 0.f, w01 = 0.f, w10 = 0.f, w11 = 0.f;
    if (n_local < ntask) {
        const float* p;
        if (n_local < 18) p = W_rxbc + (size_t)(cta * 18 + n_local) * DSSM;
        else if (hasdt && n_local == 18) p = W_rdt + (size_t)cta * DSSM;
        else p = W_out + (size_t)(cta * 8 + n_local - 18 - hasdt) * DSSM;
        w00 = p[k0]; w01 = p[k0 + 1]; w10 = p[k0 + 8]; w11 = p[k0 + 9];
    }

    unsigned short h00, l00, h01, l01, h10, l10, h11, l11;
    {
        __nv_bfloat16 h;
        h = __float2bfloat16(w00); h00 = __bfloat16_as_ushort(h);
        l00 = __bfloat16_as_ushort(__float2bfloat16(w00 - __bfloat162float(h)));
        h = __float2bfloat16(w01); h01 = __bfloat16_as_ushort(h);
        l01 = __bfloat16_as_ushort(__float2bfloat16(w01 - __bfloat162float(h)));
        h = __float2bfloat16(w10); h10 = __bfloat16_as_ushort(h);
        l10 = __bfloat16_as_ushort(__float2bfloat16(w10 - __bfloat162float(h)));
        h = __float2bfloat16(w11); h11 = __bfloat16_as_ushort(h);
        l11 = __bfloat16_as_ushort(__float2bfloat16(w11 - __bfloat162float(h)));
    }

    size_t basehi = ((size_t)(cta * 128 + s) * 2) * 256 + lane * 8 + nt * 2;
    g_wfrag[basehi]       = (unsigned)h00 | ((unsigned)h01 << 16);
    g_wfrag[basehi + 1]   = (unsigned)h10 | ((unsigned)h11 << 16);
    g_wfrag[basehi + 256] = (unsigned)l00 | ((unsigned)l01 << 16);
    g_wfrag[basehi + 257] = (unsigned)l10 | ((unsigned)l11 << 16);
}

// ---------------- kernel 1: in_proj GEMM, tf32 mma (unchanged) --------
#define ASTR 36
#define IP_AH 0
#define IP_AL (2 * 128 * ASTR)
#define IP_BH (4 * 128 * ASTR)
#define IP_BL (4 * 128 * ASTR + 2 * 64 * ASTR)
#define IP_TOTALF (4 * 128 * ASTR + 4 * 64 * ASTR)

__device__ __forceinline__ void mma_tf32(float* d, const unsigned* a, const unsigned* b) {
    asm volatile(
        "mma.sync.aligned.m16n8k8.row.col.f32.tf32.tf32.f32 "
        "{%0,%1,%2,%3}, {%4,%5,%6,%7}, {%8,%9}, {%0,%1,%2,%3};"
        : "+f"(d[0]), "+f"(d[1]), "+f"(d[2]), "+f"(d[3])
        : "r"(a[0]), "r"(a[1]), "r"(a[2]), "r"(a[3]), "r"(b[0]), "r"(b[1]));
}

__global__ __launch_bounds__(256) void inproj_kernel(const float* __restrict__ U,
                                                     const float* __restrict__ Win) {
    extern __shared__ float smf[];
    const int N = DINPROJ;
    const int K = DMODEL;

    const int tid  = threadIdx.x;
    const int lane = tid & 31;
    const int warp = tid >> 5;
    const int mbase = blockIdx.y * 128;
    const int nbase = blockIdx.x * 64;
    const int mrow0 = (warp & 3) * 32;
    const int ncol0 = (warp >> 2) * 32;

    const int arow = tid >> 1;
    const int acb  = (tid & 1) * 16;
    const int brow = tid >> 2;
    const int bcb  = (tid & 3) * 8;

    float C[2][4][4];
#pragma unroll
    for (int mt = 0; mt < 2; mt++)
#pragma unroll
        for (int nt = 0; nt < 4; nt++)
#pragma unroll
            for (int e = 0; e < 4; e++) C[mt][nt][e] = 0.0f;

    float4 aReg[4];
    float4 bReg[2];

    auto ldg_chunk = [&](int k0) {
#pragma unroll
        for (int q = 0; q < 4; q++)
            aReg[q] = *(const float4*)(U + (mbase + arow) * K + k0 + acb + q * 4);
        if (nbase + brow < N) {
#pragma unroll
            for (int q = 0; q < 2; q++)
                bReg[q] = *(const float4*)(Win + (nbase + brow) * K + k0 + bcb + q * 4);
        } else {
            bReg[0] = make_float4(0.f, 0.f, 0.f, 0.f);
            bReg[1] = make_float4(0.f, 0.f, 0.f, 0.f);
        }
    };

    auto sts_chunk = [&](int buf) {
        float* Ah = smf + IP_AH + buf * 128 * ASTR;
        float* Al = smf + IP_AL + buf * 128 * ASTR;
        float* Bh = smf + IP_BH + buf * 64 * ASTR;
        float* Bl = smf + IP_BL + buf * 64 * ASTR;
#pragma unroll
        for (int q = 0; q < 4; q++) {
            const float* v = (const float*)&aReg[q];
#pragma unroll
            for (int e = 0; e < 4; e++) {
                float x = v[e];
                unsigned hb = tf32_of(x);
                float hf = __uint_as_float(hb);
                unsigned lb = tf32_of(x - hf);
                Ah[arow * ASTR + acb + q * 4 + e] = hf;
                Al[arow * ASTR + acb + q * 4 + e] = __uint_as_float(lb);
            }
        }
#pragma unroll
        for (int q = 0; q < 2; q++) {
            const float* v = (const float*)&bReg[q];
#pragma unroll
            for (int e = 0; e < 4; e++) {
                float x = v[e];
                unsigned hb = tf32_of(x);
                float hf = __uint_as_float(hb);
                unsigned lb = tf32_of(x - hf);
                Bh[brow * ASTR + bcb + q * 4 + e] = hf;
                Bl[brow * ASTR + bcb + q * 4 + e] = __uint_as_float(lb);
            }
        }
    };

    ldg_chunk(0);
    sts_chunk(0);
    __syncthreads();

    const int NCHUNK = K / 32;
    for (int c = 0; c < NCHUNK; c++) {
        int buf = c & 1;
        if (c + 1 < NCHUNK) ldg_chunk((c + 1) * 32);

        const unsigned* Ah = (const unsigned*)(smf + IP_AH + buf * 128 * ASTR);
        const unsigned* Al = (const unsigned*)(smf + IP_AL + buf * 128 * ASTR);
        const unsigned* Bh = (const unsigned*)(smf + IP_BH + buf * 64 * ASTR);
        const unsigned* Bl = (const unsigned*)(smf + IP_BL + buf * 64 * ASTR);

#pragma unroll
        for (int ks = 0; ks < 4; ks++) {
            int kc = ks * 8;
            unsigned ah[2][4], al[2][4], bh[4][2], bl[4][2];
#pragma unroll
            for (int mt = 0; mt < 2; mt++) {
                int r0 = mrow0 + mt * 16 + (lane >> 2);
                int cc = kc + (lane & 3);
                ah[mt][0] = Ah[r0 * ASTR + cc];
                ah[mt][1] = Ah[(r0 + 8) * ASTR + cc];
                ah[mt][2] = Ah[r0 * ASTR + cc + 4];
                ah[mt][3] = Ah[(r0 + 8) * ASTR + cc + 4];
                al[mt][0] = Al[r0 * ASTR + cc];
                al[mt][1] = Al[(r0 + 8) * ASTR + cc];
                al[mt][2] = Al[r0 * ASTR + cc + 4];
                al[mt][3] = Al[(r0 + 8) * ASTR + cc + 4];
            }
#pragma unroll
            for (int nt = 0; nt < 4; nt++) {
                int n0 = ncol0 + nt * 8 + (lane >> 2);
                int kk = kc + (lane & 3);
                bh[nt][0] = Bh[n0 * ASTR + kk];
                bh[nt][1] = Bh[n0 * ASTR + kk + 4];
                bl[nt][0] = Bl[n0 * ASTR + kk];
                bl[nt][1] = Bl[n0 * ASTR + kk + 4];
            }
#pragma unroll
            for (int mt = 0; mt < 2; mt++)
#pragma unroll
                for (int nt = 0; nt < 4; nt++) {
                    mma_tf32(C[mt][nt], ah[mt], bh[nt]);
                    mma_tf32(C[mt][nt], al[mt], bh[nt]);
                    mma_tf32(C[mt][nt], ah[mt], bl[nt]);
                }
        }

        __syncthreads();
        if (c + 1 < NCHUNK) {
            sts_chunk(buf ^ 1);
            __syncthreads();
        }
    }

#pragma unroll
    for (int mt = 0; mt < 2; mt++) {
        int row = mbase + mrow0 + mt * 16 + (lane >> 2);
#pragma unroll
        for (int nt = 0; nt < 4; nt++) {
            int col = nbase + ncol0 + nt * 8 + (lane & 3) * 2;
            if (col < N) {
                g_zxbcdt[row * N + col]           = C[mt][nt][0];
                g_zxbcdt[row * N + col + 1]       = C[mt][nt][1];
                g_zxbcdt[(row + 8) * N + col]     = C[mt][nt][2];
                g_zxbcdt[(row + 8) * N + col + 1] = C[mt][nt][3];
            }
        }
    }
}

// ---------------- kernel 2: causal depthwise conv ----------------
__global__ __launch_bounds__(256) void conv_kernel(const float* __restrict__ conv_w,
                                                   const float* __restrict__ conv_b) {
    int idx = blockIdx.x * blockDim.x + threadIdx.x;
    if (idx >= BATCH * SEQLEN * CONVDIM) return;
    int c  = idx % CONVDIM;
    int bt = idx / CONVDIM;
    int t  = bt % SEQLEN;
    int b  = bt / SEQLEN;
    float accv = conv_b[c];
#pragma unroll
    for (int k = 0; k < DCONV; k++) {
        int tt = t + k - (DCONV - 1);
        if (tt >= 0)
            accv = fmaf(g_zxbcdt[(b * SEQLEN + tt) * DINPROJ + DSSM + c],
                        conv_w[c * DCONV + k], accv);
    }
    g_xbcconv[idx] = accv;
}

// ---------------- kernel 3: persistent scan, 512 threads, pipelined ----------------
__global__ __launch_bounds__(NTHR, 1) void scan_kernel(
    const float* __restrict__ dt_bias, const float* __restrict__ A_log,
    const float* __restrict__ D_param, const float* __restrict__ norm_w,
    float* __restrict__ out) {

    extern __shared__ float sm[];
    float* s_state = sm + SM_STATE;       // state[p][n], p = b_loc*64+dd, stride 132
    float* s_y     = sm + SM_Y;           // 16 warps x 512 partials / phase-B scratch
    float* s_bc    = sm + SM_BC;
    float* s_red   = sm + SM_RED;
    __shared__ unsigned s_base;

    const int tid  = threadIdx.x;
    const int cta  = blockIdx.x;
    const int lane = tid & 31;
    const int warp = tid >> 5;

    if (tid == 0) s_base = ld_acquire_u(&g_release);
    {
        int i = cta * NTHR + tid;
        if (i < 2 * 128 * 32 * 4) st_rlx_u(&g_yfrag[i], 0u);
    }
    for (int i = tid; i < 256 * 132; i += NTHR) s_state[i] = 0.0f;
    __syncthreads();
    unsigned epoch = s_base + 1;

    const int hasdt = (cta < NHEADS) ? 1 : 0;
    const int ntask = 18 + hasdt + 8;

    // ---- phase B mapping: p = tid & 255, half = tid >> 8 ----
    const int p     = tid & 255;
    const int half  = tid >> 8;
    const int h  = cta & 31;
    const int bg = cta >> 5;
    const int b_loc = p >> 6;
    const int dd    = p & 63;
    const int bglb  = bg * 4 + b_loc;
    const float Ah  = -expf(A_log[h]);
    const float dtb = dt_bias[h];
    const float Dh  = D_param[h];
    const float nw  = norm_w[h * HEADDIM + dd];
    const int n0    = half * 64;

    // Y-frag slot (based on p; only half==0 writes)
    int yk = h * HEADDIM + dd;
    int ys = yk >> 4;
    int yc = yk & 15;
    int yreg = ((yc >= 8) ? 2 : 0) + ((bglb >= 8) ? 1 : 0);
    int yln  = ((bglb & 7) << 2) | ((yc >> 1) & 3);
    int yhalf = yc & 1;
    unsigned short* yb16 = (unsigned short*)g_yfrag;
    int ywi = ((ys * 32 + yln) * 4 + yreg) * 2 + yhalf;

    // rsqrt loader mapping (tid < 128): batch rb = tid>>3, quarter rq = tid&7
    const int rb = tid >> 3;
    const int rq = tid & 7;

    grid_barrier(cta, epoch++);

    for (int t = 0; t <= SEQLEN; t++) {
        // =================== phase A: D[16,32] = Y @ W^T, pipelined ===========
        // rsqrt factors: 128 threads, 1 f4 load each + 8-lane shfl reduce
        if (tid < 128) {
            float4 v = ld_rlx_f4(g_mspart + rb * 32 + rq * 4);
            float s = (v.x + v.y) + (v.z + v.w);
            s += __shfl_xor_sync(0xffffffffu, s, 1);
            s += __shfl_xor_sync(0xffffffffu, s, 2);
            s += __shfl_xor_sync(0xffffffffu, s, 4);
            if (rq == 0) s_red[rb] = rsqrtf(s * (1.0f / (float)DSSM) + EPSV);
        }

        float acc[4][4];
#pragma unroll
        for (int nt = 0; nt < 4; nt++)
#pragma unroll
            for (int e = 0; e < 4; e++) acc[nt][e] = 0.0f;

        uint4 wb[2][4];
        F4U yhb[2], ylb[2];
        auto load_slice = [&](int buf, int sl) {
            int s = (warp << 3) + sl;
            const uint4* wph = (const uint4*)(g_wfrag + ((size_t)(cta * 128 + s) * 2) * 256 + lane * 8);
            const uint4* wpl = (const uint4*)(g_wfrag + ((size_t)(cta * 128 + s) * 2 + 1) * 256 + lane * 8);
            yhb[buf].f = ld_rlx_f4((const float*)(g_yfrag + (s * 32 + lane) * 4));
            ylb[buf].f = ld_rlx_f4((const float*)(g_yfrag + 16384 + (s * 32 + lane) * 4));
            wb[buf][0] = wph[0];
            wb[buf][1] = wph[1];
            wb[buf][2] = wpl[0];
            wb[buf][3] = wpl[1];
        };

        load_slice(0, 0);
#pragma unroll
        for (int sl = 0; sl < 8; sl++) {
            int cb = sl & 1;
            if (sl < 7) load_slice(cb ^ 1, sl + 1);    // prefetch next slice first

            mma_bf16(acc[0], yhb[cb].v, wb[cb][0].x, wb[cb][0].y);
            mma_bf16(acc[0], ylb[cb].v, wb[cb][0].x, wb[cb][0].y);
            mma_bf16(acc[0], yhb[cb].v, wb[cb][2].x, wb[cb][2].y);

            mma_bf16(acc[1], yhb[cb].v, wb[cb][0].z, wb[cb][0].w);
            mma_bf16(acc[1], ylb[cb].v, wb[cb][0].z, wb[cb][0].w);
            mma_bf16(acc[1], yhb[cb].v, wb[cb][2].z, wb[cb][2].w);

            mma_bf16(acc[2], yhb[cb].v, wb[cb][1].x, wb[cb][1].y);
            mma_bf16(acc[2], ylb[cb].v, wb[cb][1].x, wb[cb][1].y);
            mma_bf16(acc[2], yhb[cb].v, wb[cb][3].x, wb[cb][3].y);

            mma_bf16(acc[3], yhb[cb].v, wb[cb][1].z, wb[cb][1].w);
            mma_bf16(acc[3], ylb[cb].v, wb[cb][1].z, wb[cb][1].w);
            mma_bf16(acc[3], yhb[cb].v, wb[cb][3].z, wb[cb][3].w);
        }

        {
            int bq = lane >> 2;
            int c2 = (lane & 3) * 2;
            float* wp = s_y + warp * 512;
#pragma unroll
            for (int nt = 0; nt < 4; nt++) {
                *(float2*)(wp + bq * 32 + nt * 8 + c2)       = make_float2(acc[nt][0], acc[nt][1]);
                *(float2*)(wp + (bq + 8) * 32 + nt * 8 + c2) = make_float2(acc[nt][2], acc[nt][3]);
            }
        }
        __syncthreads();

        // reduce 16 warp planes; one group per thread
        {
            int g = tid;
            int b = g >> 5;
            int r = g & 31;
            if (r < ntask) {
                float sum = 0.0f;
#pragma unroll
                for (int w = 0; w < 16; w++) sum += s_y[w * 512 + g];
                float val = sum * s_red[b];
                if (r < 18) {
                    if (t < SEQLEN) {
                        int idxv = cta * 18 + r;
                        float base = g_xbcconv[(b * SEQLEN + t) * CONVDIM + idxv];
                        st_rlx_f(&g_act[b * ACTDIM + idxv], silu_f(base + val));
                    }
                } else if (hasdt && r == 18) {
                    if (t < SEQLEN) {
                        float base = g_zxbcdt[(b * SEQLEN + t) * DINPROJ + (DSSM + CONVDIM) + cta];
                        st_rlx_f(&g_act[b * ACTDIM + CONVDIM + cta], silu_f(base + val));
                    }
                } else {
                    int idxv = cta * 8 + (r - 18 - hasdt);
                    if (t >= 1) out[(b * SEQLEN + (t - 1)) * DMODEL + idxv] = val;
                }
            }
        }

        if (t == SEQLEN) break;

        grid_barrier(cta, epoch++);   // act(t) visible

        // =================== phase B (n-range split across halves) ===================
        // issue critical-path scalar loads FIRST (overlap Bv/Cv staging)
        float x   = ld_rlx_f(&g_act[bglb * ACTDIM + h * HEADDIM + dd]);
        float dtr = ld_rlx_f(&g_act[bglb * ACTDIM + CONVDIM + h]);
        float z   = g_zxbcdt[(bglb * SEQLEN + t) * DINPROJ + h * HEADDIM + dd];

        {
            int i = tid * 2;           // 512 threads x float2 = 1024 floats
            int bl = i >> 8, k = i & 255;
            float2 v = ld_rlx_f2((const float*)&g_act[(bg * 4 + bl) * ACTDIM + DSSM + k]);
            *(float2*)(s_bc + i) = v;
        }
        __syncthreads();

        float g;
        {
            float dt_v = softplus_f(dtr + dtb);
            float dA  = expf(dt_v * Ah);
            float coef = dt_v * x;

            unsigned long long dA2 = pk2(dA, dA);
            unsigned long long cf2 = pk2(coef, coef);
            unsigned long long acc2 = 0ULL;

            const float* bvp = s_bc + b_loc * 256 + n0;
            const float* cvp = s_bc + b_loc * 256 + 128 + n0;
            float* sp = s_state + p * 132 + n0;
#pragma unroll 4
            for (int n = 0; n < 64; n += 4) {
                F4U sv, bv, cv;
                sv.f = *(float4*)(sp + n);
                bv.f = *(const float4*)(bvp + n);
                cv.f = *(const float4*)(cvp + n);
                sv.u[0] = fma2(sv.u[0], dA2, mul2(cf2, bv.u[0]));
                sv.u[1] = fma2(sv.u[1], dA2, mul2(cf2, bv.u[1]));
                acc2 = fma2(sv.u[0], cv.u[0], acc2);
                acc2 = fma2(sv.u[1], cv.u[1], acc2);
                *(float4*)(sp + n) = sv.f;
            }
            float alo, ahi;
            upk2(acc2, alo, ahi);
            s_y[tid] = alo + ahi;     // partial dot over this half's n-range
        }
        __syncthreads();

        if (half == 0) {
            float accv = s_y[tid] + s_y[tid + 256];
            float y = fmaf(Dh, x, accv);
            g = y * silu_f(z);

            float yv = g * nw;
            __nv_bfloat16 hb = __float2bfloat16(yv);
            float hf = __bfloat162float(hb);
            __nv_bfloat16 lb = __float2bfloat16(yv - hf);
            st_rlx_b16(yb16 + ywi, __bfloat16_as_ushort(hb));
            st_rlx_b16(yb16 + 32768 + ywi, __bfloat16_as_ushort(lb));

            float gsq = g * g;
#pragma unroll
            for (int off = 16; off > 0; off >>= 1)
                gsq += __shfl_xor_sync(0xffffffffu, gsq, off);
            if (lane == 0) s_red[16 + warp] = gsq;   // warps 0..7
        }
        __syncthreads();

        if (tid < 4) {
            float part = s_red[16 + 2 * tid] + s_red[16 + 2 * tid + 1];
            st_rlx_f(&g_mspart[(bg * 4 + tid) * 32 + h], part);
        }

        grid_barrier(cta, epoch++);   // yfrags + partials visible
    }
}

// ---------------- launcher ----------------
extern "C" void kernel_launch(void* const* d_in, const int* in_sizes, int n_in,
                              void* d_out, int out_size) {
    const float* u       = (const float*)d_in[0];
    const float* W_in    = (const float*)d_in[1];
    const float* conv_w  = (const float*)d_in[2];
    const float* conv_b  = (const float*)d_in[3];
    const float* W_rxbc  = (const float*)d_in[4];
    const float* W_rdt   = (const float*)d_in[5];
    const float* dt_bias = (const float*)d_in[6];
    const float* A_log   = (const float*)d_in[7];
    const float* D_param = (const float*)d_in[8];
    const float* norm_w  = (const float*)d_in[9];
    const float* W_out   = (const float*)d_in[10];
    float* out = (float*)d_out;

    static int attr_set = 0;
    const int SCAN_SMEM = SM_TOTALF * 4;
    const int IP_SMEM   = IP_TOTALF * 4;
    if (!attr_set) {
        cudaFuncSetAttribute(scan_kernel, cudaFuncAttributeMaxDynamicSharedMemorySize, SCAN_SMEM);
        cudaFuncSetAttribute(inproj_kernel, cudaFuncAttributeMaxDynamicSharedMemorySize, IP_SMEM);
        attr_set = 1;
    }

    wfrag_kernel<<<8192, 256>>>(W_rxbc, W_rdt, W_out);

    dim3 gIn((DINPROJ + 63) / 64, (BATCH * SEQLEN) / 128);
    inproj_kernel<<<gIn, 256, IP_SMEM>>>(u, W_in);

    int convN = BATCH * SEQLEN * CONVDIM;
    conv_kernel<<<(convN + 255) / 256, 256>>>(conv_w, conv_b);

    scan_kernel<<<NCTA, NTHR, SCAN_SMEM>>>(dt_bias, A_log, D_param, norm_w, out);
}